// round 2
// baseline (speedup 1.0000x reference)
#include <cuda_runtime.h>
#include <cuda_bf16.h>
#include <mma.h>
#include <math.h>
#include <cstdint>

using namespace nvcuda;

// ---------------------------------------------------------------------------
// Problem constants
// ---------------------------------------------------------------------------
static constexpr int B_    = 4;
static constexpr int LV    = 768;
static constexpr int LE    = 64;
static constexpr int LT    = 832;    // LV + LE
static constexpr int LP    = 896;    // LT padded to multiple of 128
static constexpr int DV    = 2048;
static constexpr int DE    = 1024;
static constexpr int H_    = 8;
static constexpr int DH_   = 256;
static constexpr int HD    = 2048;   // H_*DH_
static constexpr float SCALE_ = 0.0625f; // 1/sqrt(256)

// ---------------------------------------------------------------------------
// Scratch layout (single __device__ array; zero-initialized => pad rows of
// Q/K/V stay 0 forever since we never write them)
// ---------------------------------------------------------------------------
static constexpr size_t SZ_QV = (size_t)B_*LV*HD;      // 6,291,456
static constexpr size_t SZ_QE = (size_t)B_*LE*HD;      //   524,288
static constexpr size_t SZ_Qp = (size_t)B_*H_*LP*DH_;  // 7,340,032
static constexpr size_t SZ_Sp = (size_t)B_*H_*LP*LP;   // 25,690,112
static constexpr size_t SZ_AOp= (size_t)B_*LP*HD;      // 7,340,032

static constexpr size_t OFF_QV = 0;
static constexpr size_t OFF_KV = OFF_QV + SZ_QV;
static constexpr size_t OFF_VV = OFF_KV + SZ_QV;
static constexpr size_t OFF_QE = OFF_VV + SZ_QV;
static constexpr size_t OFF_KE = OFF_QE + SZ_QE;
static constexpr size_t OFF_VE = OFF_KE + SZ_QE;
static constexpr size_t OFF_Q  = OFF_VE + SZ_QE;
static constexpr size_t OFF_K  = OFF_Q  + SZ_Qp;
static constexpr size_t OFF_V  = OFF_K  + SZ_Qp;
static constexpr size_t OFF_S  = OFF_V  + SZ_Qp;
static constexpr size_t OFF_AO = OFF_S  + SZ_Sp;
static constexpr size_t OFF_AV = OFF_AO + SZ_AOp;
static constexpr size_t OFF_AE = OFF_AV + SZ_QV;
static constexpr size_t SCRATCH_TOTAL = OFF_AE + SZ_QE;

__device__ float g_scratch[SCRATCH_TOTAL];

// ---------------------------------------------------------------------------
// cp.async helpers
// ---------------------------------------------------------------------------
__device__ __forceinline__ void cp_async16(void* smem_dst, const void* gmem_src) {
    uint32_t s = (uint32_t)__cvta_generic_to_shared(smem_dst);
    asm volatile("cp.async.cg.shared.global [%0], [%1], 16;\n" :: "r"(s), "l"(gmem_src));
}
__device__ __forceinline__ void cp_commit() {
    asm volatile("cp.async.commit_group;\n");
}
template<int N>
__device__ __forceinline__ void cp_wait() {
    asm volatile("cp.async.wait_group %0;\n" :: "n"(N));
}

// ---------------------------------------------------------------------------
// tf32 WMMA GEMM, 128x128 block tile, BK=32, 256 threads, double-buffered
// cp.async pipeline. C = alpha * A @ B (or A @ B^T when TB).
// Requires M%128==0, N%128==0, K%32==0, all leading dims %4==0.
// Batched via blockIdx.z: (b,h) = (z/Hdiv, z%Hdiv).
// ---------------------------------------------------------------------------
static constexpr int BM = 128, BN = 128, BK = 32;
static constexpr int LDA_S = BK + 4;            // 36
static constexpr int LDB_S_RM = BN + 4;         // 132 (B row-major [k][n])
static constexpr int LDB_S_CM = BK + 4;         // 36  (B [n][k])

template<bool TB>
__global__ __launch_bounds__(256, 2)
void gemm2(const float* __restrict__ A, const float* __restrict__ B,
           float* __restrict__ C,
           int K, int lda, int ldb, int ldc,
           long long sAb, long long sAh,
           long long sBb, long long sBh,
           long long sCb, long long sCh,
           int Hdiv, float alpha)
{
    {
        int z  = blockIdx.z;
        int bb = z / Hdiv;
        int hh = z - bb * Hdiv;
        A += bb * sAb + hh * sAh;
        B += bb * sBb + hh * sBh;
        C += bb * sCb + hh * sCh;
    }

    const int m0  = blockIdx.y * BM;
    const int n0  = blockIdx.x * BN;
    const int tid = threadIdx.x;

    extern __shared__ float sm[];
    float* As = sm;                              // 2 x 128 x 36
    float* Bs = sm + 2 * BM * LDA_S;             // 2 x (TB ? 128x36 : 32x132)
    constexpr int ASZ = BM * LDA_S;              // per-buffer A floats
    constexpr int BSZ = TB ? (BN * LDB_S_CM) : (BK * LDB_S_RM);

    // ---- tile loader: stage kt into buffer buf ----
    auto load_tile = [&](int buf, int kt) {
        const int k0 = kt * BK;
        // A: 128 rows x 32 cols = 1024 x 16B chunks, 4 per thread
#pragma unroll
        for (int i = 0; i < 4; i++) {
            int idx = tid + 256 * i;             // 0..1023
            int r = idx >> 3;                    // row 0..127
            int c = (idx & 7) << 2;              // col 0,4,..,28
            cp_async16(&As[buf * ASZ + r * LDA_S + c],
                       A + (size_t)(m0 + r) * lda + k0 + c);
        }
        if (!TB) {
            // B[K,N]: tile 32(k) x 128(n)
#pragma unroll
            for (int i = 0; i < 4; i++) {
                int idx = tid + 256 * i;
                int r = idx >> 5;                // k 0..31
                int c = (idx & 31) << 2;         // n 0..124
                cp_async16(&Bs[buf * BSZ + r * LDB_S_RM + c],
                           B + (size_t)(k0 + r) * ldb + n0 + c);
            }
        } else {
            // B[N,K]: tile 128(n) x 32(k)
#pragma unroll
            for (int i = 0; i < 4; i++) {
                int idx = tid + 256 * i;
                int r = idx >> 3;                // n 0..127
                int c = (idx & 7) << 2;          // k 0..28
                cp_async16(&Bs[buf * BSZ + r * LDB_S_CM + c],
                           B + (size_t)(n0 + r) * ldb + k0 + c);
            }
        }
    };

    // warp layout: 2 (m) x 4 (n) warps; warp tile 64 x 32
    const int warp = tid >> 5;
    const int wm = (warp >> 2) * 64;
    const int wn = (warp & 3) * 32;

    wmma::fragment<wmma::accumulator, 16, 16, 8, float> acc[4][2];
#pragma unroll
    for (int i = 0; i < 4; i++)
#pragma unroll
        for (int j = 0; j < 2; j++)
            wmma::fill_fragment(acc[i][j], 0.0f);

    const int nk = K / BK;
    load_tile(0, 0);
    cp_commit();

    for (int kt = 0; kt < nk; kt++) {
        const int cur = kt & 1;
        if (kt + 1 < nk) { load_tile(cur ^ 1, kt + 1); cp_commit(); cp_wait<1>(); }
        else             { cp_wait<0>(); }
        __syncthreads();

        const float* Ab = &As[cur * ASZ];
        const float* Bb = &Bs[cur * BSZ];

#pragma unroll
        for (int kk = 0; kk < BK; kk += 8) {
            wmma::fragment<wmma::matrix_a, 16, 16, 8, wmma::precision::tf32,
                           wmma::row_major> af[4];
#pragma unroll
            for (int i = 0; i < 4; i++) {
                wmma::load_matrix_sync(af[i], Ab + (wm + 16 * i) * LDA_S + kk, LDA_S);
#pragma unroll
                for (int t = 0; t < af[i].num_elements; t++)
                    af[i].x[t] = wmma::__float_to_tf32(af[i].x[t]);
            }
            if (!TB) {
                wmma::fragment<wmma::matrix_b, 16, 16, 8, wmma::precision::tf32,
                               wmma::row_major> bf[2];
#pragma unroll
                for (int j = 0; j < 2; j++) {
                    wmma::load_matrix_sync(bf[j], Bb + kk * LDB_S_RM + wn + 16 * j,
                                           LDB_S_RM);
#pragma unroll
                    for (int t = 0; t < bf[j].num_elements; t++)
                        bf[j].x[t] = wmma::__float_to_tf32(bf[j].x[t]);
                }
#pragma unroll
                for (int i = 0; i < 4; i++)
#pragma unroll
                    for (int j = 0; j < 2; j++)
                        wmma::mma_sync(acc[i][j], af[i], bf[j], acc[i][j]);
            } else {
                wmma::fragment<wmma::matrix_b, 16, 16, 8, wmma::precision::tf32,
                               wmma::col_major> bf[2];
#pragma unroll
                for (int j = 0; j < 2; j++) {
                    wmma::load_matrix_sync(bf[j], Bb + (wn + 16 * j) * LDB_S_CM + kk,
                                           LDB_S_CM);
#pragma unroll
                    for (int t = 0; t < bf[j].num_elements; t++)
                        bf[j].x[t] = wmma::__float_to_tf32(bf[j].x[t]);
                }
#pragma unroll
                for (int i = 0; i < 4; i++)
#pragma unroll
                    for (int j = 0; j < 2; j++)
                        wmma::mma_sync(acc[i][j], af[i], bf[j], acc[i][j]);
            }
        }
        __syncthreads();
    }

#pragma unroll
    for (int i = 0; i < 4; i++)
#pragma unroll
        for (int j = 0; j < 2; j++) {
#pragma unroll
            for (int t = 0; t < acc[i][j].num_elements; t++)
                acc[i][j].x[t] *= alpha;
            wmma::store_matrix_sync(
                C + (size_t)(m0 + wm + 16 * i) * ldc + n0 + wn + 16 * j,
                acc[i][j], ldc, wmma::mem_row_major);
        }
}

// ---------------------------------------------------------------------------
// Gather projected QKV into padded [B,H,LP,DH] layout + RoPE on Q,K
// ---------------------------------------------------------------------------
__global__ void assemble_rope(const float* __restrict__ Qv, const float* __restrict__ Kv,
                              const float* __restrict__ Vv,
                              const float* __restrict__ Qe, const float* __restrict__ Ke,
                              const float* __restrict__ Ve,
                              const int* __restrict__ pos_ids,
                              float* __restrict__ Q, float* __restrict__ K,
                              float* __restrict__ V)
{
    int idx = blockIdx.x * blockDim.x + threadIdx.x;
    const int TOTAL = B_ * H_ * LT * (DH_ / 2);
    if (idx >= TOTAL) return;

    int i = idx & 127;
    int t = idx >> 7;
    int l = t % LT;  t /= LT;
    int h = t % H_;
    int b = t / H_;

    int pos = pos_ids[b * LT + l];
    const float LN_BASE_OVER_128 = 9.210340371976184f / 128.0f;
    float ang = (float)pos * expf(-LN_BASE_OVER_128 * (float)i);
    float cs = cosf(ang), sn = sinf(ang);

    const float *sq, *sk, *sv;
    size_t row;
    if (l < LV) { row = (size_t)(b * LV + l); sq = Qv; sk = Kv; sv = Vv; }
    else        { row = (size_t)(b * LE + (l - LV)); sq = Qe; sk = Ke; sv = Ve; }
    size_t src = row * HD + h * DH_ + i;

    size_t dst = (((size_t)(b * H_ + h) * LP) + l) * DH_ + i;

    float q1 = sq[src], q2 = sq[src + 128];
    Q[dst]       = q1 * cs - q2 * sn;
    Q[dst + 128] = q2 * cs + q1 * sn;

    float k1 = sk[src], k2 = sk[src + 128];
    K[dst]       = k1 * cs - k2 * sn;
    K[dst + 128] = k2 * cs + k1 * sn;

    V[dst]       = sv[src];
    V[dst + 128] = sv[src + 128];
}

// ---------------------------------------------------------------------------
// Row softmax over first LT cols of padded-stride S rows, + additive mask
// One block (256 thr) per real row; row = (b*H + h)*LT + q
// ---------------------------------------------------------------------------
__global__ void softmax_rows(float* __restrict__ S, const float* __restrict__ mask)
{
    int row = blockIdx.x;
    int z = row / LT, q = row - z * LT;
    int b = z / H_;
    const float* mrow = mask + ((size_t)b * LT + q) * LT;
    float* srow = S + ((size_t)z * LP + q) * LP;

    __shared__ float red[256];
    int tid = threadIdx.x;

    float m = -1e30f;
    for (int k = tid; k < LT; k += 256) {
        float v = srow[k] + mrow[k];
        srow[k] = v;
        m = fmaxf(m, v);
    }
    red[tid] = m; __syncthreads();
    for (int s = 128; s > 0; s >>= 1) {
        if (tid < s) red[tid] = fmaxf(red[tid], red[tid + s]);
        __syncthreads();
    }
    m = red[0]; __syncthreads();

    float sum = 0.0f;
    for (int k = tid; k < LT; k += 256) {
        float e = __expf(srow[k] - m);
        srow[k] = e;
        sum += e;
    }
    red[tid] = sum; __syncthreads();
    for (int s = 128; s > 0; s >>= 1) {
        if (tid < s) red[tid] += red[tid + s];
        __syncthreads();
    }
    float inv = 1.0f / red[0];
    for (int k = tid; k < LT; k += 256) srow[k] *= inv;
}

// ---------------------------------------------------------------------------
// Split padded attn_out [B, LP, HD] into vlm [B*LV, HD] and exp [B*LE, HD]
// ---------------------------------------------------------------------------
__global__ void split_attn(const float* __restrict__ AO,
                           float* __restrict__ AVb, float* __restrict__ AEb)
{
    size_t idx = (size_t)blockIdx.x * blockDim.x + threadIdx.x;
    const size_t TOTAL = (size_t)B_ * LT * HD;
    if (idx >= TOTAL) return;
    int c = (int)(idx & (HD - 1));
    int t = (int)(idx >> 11);
    int l = t % LT, b = t / LT;
    float v = AO[((size_t)(b * LP + l) << 11) + c];
    if (l < LV) AVb[((size_t)(b * LV + l) << 11) + c] = v;
    else        AEb[((size_t)(b * LE + (l - LV)) << 11) + c] = v;
}

// ---------------------------------------------------------------------------
// Host side
// ---------------------------------------------------------------------------
extern "C" void kernel_launch(void* const* d_in, const int* in_sizes, int n_in,
                              void* d_out, int out_size)
{
    const float* vlm_hidden = (const float*)d_in[0];
    const float* exp_hidden = (const float*)d_in[1];
    const float* attn_mask  = (const float*)d_in[2];
    const int*   pos_ids    = (const int*)  d_in[3];
    const float* wq_v = (const float*)d_in[4];
    const float* wk_v = (const float*)d_in[5];
    const float* wv_v = (const float*)d_in[6];
    const float* wo_v = (const float*)d_in[7];
    const float* wq_e = (const float*)d_in[8];
    const float* wk_e = (const float*)d_in[9];
    const float* wv_e = (const float*)d_in[10];
    const float* wo_e = (const float*)d_in[11];
    float* out = (float*)d_out;

    float* sc = nullptr;
    cudaGetSymbolAddress((void**)&sc, g_scratch);

    float* Qv = sc + OFF_QV; float* Kv = sc + OFF_KV; float* Vv = sc + OFF_VV;
    float* Qe = sc + OFF_QE; float* Ke = sc + OFF_KE; float* Ve = sc + OFF_VE;
    float* Q  = sc + OFF_Q;  float* K  = sc + OFF_K;  float* V  = sc + OFF_V;
    float* S  = sc + OFF_S;
    float* AO = sc + OFF_AO; float* AVb = sc + OFF_AV; float* AEb = sc + OFF_AE;

    const int MV = B_ * LV;   // 3072
    const int ME = B_ * LE;   // 256

    // opt-in smem sizes
    constexpr int SMEM_NT = 4 * (2 * BM * LDA_S + 2 * BK * LDB_S_RM); // 70656
    constexpr int SMEM_T  = 4 * (2 * BM * LDA_S + 2 * BN * LDB_S_CM); // 73728
    cudaFuncSetAttribute((const void*)gemm2<false>,
                         cudaFuncAttributeMaxDynamicSharedMemorySize, SMEM_NT);
    cudaFuncSetAttribute((const void*)gemm2<true>,
                         cudaFuncAttributeMaxDynamicSharedMemorySize, SMEM_T);

    // ---- QKV projections ----
    {
        dim3 g(HD / BN, MV / BM, 1);
        gemm2<false><<<g, 256, SMEM_NT>>>(vlm_hidden, wq_v, Qv, DV,
                                          DV, HD, HD, 0,0,0,0,0,0, 1, 1.0f);
        gemm2<false><<<g, 256, SMEM_NT>>>(vlm_hidden, wk_v, Kv, DV,
                                          DV, HD, HD, 0,0,0,0,0,0, 1, 1.0f);
        gemm2<false><<<g, 256, SMEM_NT>>>(vlm_hidden, wv_v, Vv, DV,
                                          DV, HD, HD, 0,0,0,0,0,0, 1, 1.0f);
    }
    {
        dim3 g(HD / BN, ME / BM, 1);
        gemm2<false><<<g, 256, SMEM_NT>>>(exp_hidden, wq_e, Qe, DE,
                                          DE, HD, HD, 0,0,0,0,0,0, 1, 1.0f);
        gemm2<false><<<g, 256, SMEM_NT>>>(exp_hidden, wk_e, Ke, DE,
                                          DE, HD, HD, 0,0,0,0,0,0, 1, 1.0f);
        gemm2<false><<<g, 256, SMEM_NT>>>(exp_hidden, wv_e, Ve, DE,
                                          DE, HD, HD, 0,0,0,0,0,0, 1, 1.0f);
    }

    // ---- gather + RoPE into padded [B,H,LP,DH] ----
    {
        int total = B_ * H_ * LT * (DH_ / 2);
        assemble_rope<<<(total + 255) / 256, 256>>>(Qv, Kv, Vv, Qe, Ke, Ve,
                                                    pos_ids, Q, K, V);
    }

    // ---- scores = scale * Q @ K^T (padded LP x LP per head) ----
    {
        long long sH = (long long)LP * DH_;
        long long sB = (long long)H_ * LP * DH_;
        long long cH = (long long)LP * LP;
        long long cB = (long long)H_ * LP * LP;
        dim3 g(LP / BN, LP / BM, B_ * H_);
        gemm2<true><<<g, 256, SMEM_T>>>(Q, K, S, DH_,
                                        DH_, DH_, LP,
                                        sB, sH, sB, sH, cB, cH, H_, SCALE_);
    }

    // ---- softmax (+mask) in place ----
    softmax_rows<<<B_ * H_ * LT, 256>>>(S, attn_mask);

    // ---- attn_out = P @ V into padded [B, LP, H*DH] ----
    {
        long long aH = (long long)LP * LP;
        long long aB = (long long)H_ * LP * LP;
        long long bH = (long long)LP * DH_;
        long long bB = (long long)H_ * LP * DH_;
        long long cB = (long long)LP * HD;
        long long cH = (long long)DH_;
        dim3 g(DH_ / BN, LP / BM, B_ * H_);
        gemm2<false><<<g, 256, SMEM_NT>>>(S, V, AO, LT,
                                          LP, DH_, HD,
                                          aB, aH, bB, bH, cB, cH, H_, 1.0f);
    }

    // ---- split into contiguous vlm / exp row blocks ----
    {
        size_t total = (size_t)B_ * LT * HD;
        split_attn<<<(unsigned)((total + 255) / 256), 256>>>(AO, AVb, AEb);
    }

    // ---- output projections straight into d_out ----
    {
        dim3 g(DV / BN, MV / BM, 1);
        gemm2<false><<<g, 256, SMEM_NT>>>(AVb, wo_v, out, HD,
                                          HD, DV, DV, 0,0,0,0,0,0, 1, 1.0f);
    }
    {
        float* out_e = out + (size_t)MV * DV;
        dim3 g(DE / BN, ME / BM, 1);
        gemm2<false><<<g, 256, SMEM_NT>>>(AEb, wo_e, out_e, HD,
                                          HD, DE, DE, 0,0,0,0,0,0, 1, 1.0f);
    }
}

// round 4
// speedup vs baseline: 2.6747x; 2.6747x over previous
#include <cuda_runtime.h>
#include <cuda_bf16.h>
#include <math.h>
#include <cstdint>

// ---------------------------------------------------------------------------
// Problem constants
// ---------------------------------------------------------------------------
static constexpr int B_    = 4;
static constexpr int LV    = 768;
static constexpr int LE    = 64;
static constexpr int LT    = 832;
static constexpr int LP    = 896;    // padded to multiple of 128
static constexpr int DV    = 2048;
static constexpr int DE    = 1024;
static constexpr int H_    = 8;
static constexpr int DH_   = 256;
static constexpr int HD    = 2048;
static constexpr float SCALE_ = 0.0625f;

// ---------------------------------------------------------------------------
// Scratch (zero-initialized __device__ array; pad rows never written stay 0)
// ---------------------------------------------------------------------------
static constexpr size_t SZ_QKVV = (size_t)B_*LV*6144;
static constexpr size_t SZ_QKVE = (size_t)B_*LE*6144;
static constexpr size_t SZ_QP   = (size_t)B_*H_*LP*DH_;
static constexpr size_t SZ_S    = (size_t)B_*H_*LP*LP;
static constexpr size_t SZ_AO   = (size_t)B_*LP*HD;
static constexpr size_t SZ_WTV  = (size_t)6144*2048;
static constexpr size_t SZ_WTE  = (size_t)6144*1024;
static constexpr size_t SZ_WOV  = (size_t)2048*2048;
static constexpr size_t SZ_WOE  = (size_t)1024*2048;
static constexpr size_t SZ_HIDV = (size_t)B_*LV*DV;
static constexpr size_t SZ_HIDE = (size_t)B_*LE*DE;

static constexpr size_t OFF_QKVV = 0;
static constexpr size_t OFF_QKVE = OFF_QKVV + SZ_QKVV;
static constexpr size_t OFF_Q    = OFF_QKVE + SZ_QKVE;
static constexpr size_t OFF_K    = OFF_Q    + SZ_QP;
static constexpr size_t OFF_V    = OFF_K    + SZ_QP;
static constexpr size_t OFF_VT   = OFF_V    + SZ_QP;
static constexpr size_t OFF_S    = OFF_VT   + SZ_QP;
static constexpr size_t OFF_AO   = OFF_S    + SZ_S;
static constexpr size_t OFF_WTV  = OFF_AO   + SZ_AO;
static constexpr size_t OFF_WTE  = OFF_WTV  + SZ_WTV;
static constexpr size_t OFF_WOV  = OFF_WTE  + SZ_WTE;
static constexpr size_t OFF_WOE  = OFF_WOV  + SZ_WOV;
static constexpr size_t OFF_HIDV = OFF_WOE  + SZ_WOE;
static constexpr size_t OFF_HIDE = OFF_HIDV + SZ_HIDV;
static constexpr size_t SCRATCH_TOTAL = OFF_HIDE + SZ_HIDE;

__device__ float g_scratch[SCRATCH_TOTAL];

// ---------------------------------------------------------------------------
// Helpers
// ---------------------------------------------------------------------------
__device__ __forceinline__ uint32_t smem_u32_of(const void* p) {
    uint32_t a;
    asm("{ .reg .u64 t; cvta.to.shared.u64 t, %1; cvt.u32.u64 %0, t; }"
        : "=r"(a) : "l"(p));
    return a;
}
__device__ __forceinline__ void cp_async16(uint32_t saddr, const void* gsrc) {
    asm volatile("cp.async.cg.shared.global [%0], [%1], 16;\n"
                 :: "r"(saddr), "l"(gsrc));
}
__device__ __forceinline__ void cp_commit() {
    asm volatile("cp.async.commit_group;\n");
}
template<int N>
__device__ __forceinline__ void cp_wait() {
    asm volatile("cp.async.wait_group %0;\n" :: "n"(N));
}
__device__ __forceinline__ float tf32r(float x) {
    uint32_t u;
    asm("cvt.rna.tf32.f32 %0, %1;" : "=r"(u) : "f"(x));
    return __uint_as_float(u);
}
__device__ __forceinline__ void ldsm_x4(uint32_t& r0, uint32_t& r1,
                                        uint32_t& r2, uint32_t& r3,
                                        uint32_t addr) {
    asm volatile("ldmatrix.sync.aligned.m8n8.x4.shared.b16 {%0,%1,%2,%3}, [%4];\n"
                 : "=r"(r0), "=r"(r1), "=r"(r2), "=r"(r3) : "r"(addr));
}
__device__ __forceinline__ void mma_tf32(float* c, const uint32_t* a,
                                         const uint32_t* b) {
    asm volatile(
        "mma.sync.aligned.m16n8k8.row.col.f32.tf32.tf32.f32 "
        "{%0,%1,%2,%3}, {%4,%5,%6,%7}, {%8,%9}, {%0,%1,%2,%3};\n"
        : "+f"(c[0]), "+f"(c[1]), "+f"(c[2]), "+f"(c[3])
        : "r"(a[0]), "r"(a[1]), "r"(a[2]), "r"(a[3]), "r"(b[0]), "r"(b[1]));
}

// ---------------------------------------------------------------------------
// tf32 mma.sync GEMM: D[m,n] = alpha * sum_k A[m,k]*B[n,k]
// Tile 128x128, BK=32, 3-stage cp.async, 256 threads (8 warps, 64x32 each).
// Operands MUST be pre-rounded to tf32. N%128==0, K%32==0.
// A row guard via Mvalid (loads clamped, stores masked).
// Batched via blockIdx.z: (bb,hh) = (z/Hdiv, z%Hdiv).
// ---------------------------------------------------------------------------
static constexpr int STAGES = 3;
static constexpr int STAGE_BYTES = 2 * 128 * 32 * 4;       // 32 KB
static constexpr int GEMM_SMEM = STAGES * STAGE_BYTES + 1024;

__global__ __launch_bounds__(256, 2)
void gemm_mma(const float* __restrict__ A, const float* __restrict__ B,
              float* __restrict__ C,
              int Kdim, int lda, int ldb, int ldc,
              long long sAb, long long sAh,
              long long sBb, long long sBh,
              long long sCb, long long sCh,
              int Hdiv, float alpha, int Mvalid, int roundOut)
{
    {
        int z  = blockIdx.z;
        int bb = z / Hdiv;
        int hh = z - bb * Hdiv;
        A += bb * sAb + hh * sAh;
        B += bb * sBb + hh * sBh;
        C += bb * sCb + hh * sCh;
    }
    const int m0  = blockIdx.y * 128;
    const int n0  = blockIdx.x * 128;
    const int tid = threadIdx.x;
    const int wid = tid >> 5;
    const int lane = tid & 31;
    const int wm = (wid >> 2) * 64;      // 2 warp rows
    const int wn = (wid & 3) * 32;       // 4 warp cols

    extern __shared__ float dsm[];
    const uint32_t smem0 = (smem_u32_of(dsm) + 127u) & ~127u;

    // stage loader: 2048 x 16B chunks (A then B), 8 per thread
    auto load_stage = [&](int st, int kt) {
        const int k0 = kt * 32;
        const uint32_t sbase = smem0 + (uint32_t)st * STAGE_BYTES;
#pragma unroll
        for (int t = 0; t < 8; t++) {
            int idx = tid + t * 256;
            int isB = idx >> 10;
            int u   = idx & 1023;
            int r   = u >> 3;
            int c4  = u & 7;
            uint32_t dst = sbase + (uint32_t)isB * 16384u
                         + (uint32_t)(r * 128 + ((c4 ^ (r & 7)) << 4));
            const float* src;
            if (isB) {
                src = B + (size_t)(n0 + r) * ldb + k0 + c4 * 4;
            } else {
                int rr = (m0 + r < Mvalid) ? r : 0;
                src = A + (size_t)(m0 + rr) * lda + k0 + c4 * 4;
            }
            cp_async16(dst, src);
        }
    };

    float acc[4][4][4];
#pragma unroll
    for (int i = 0; i < 4; i++)
#pragma unroll
        for (int j = 0; j < 4; j++)
#pragma unroll
            for (int t = 0; t < 4; t++) acc[i][j][t] = 0.0f;

    const int nk = Kdim / 32;
    load_stage(0, 0); cp_commit();
    load_stage(1, 1); cp_commit();

    for (int i = 0; i < nk; i++) {
        const int st = i % STAGES;
        cp_wait<1>();
        __syncthreads();
        if (i + 2 < nk) load_stage((i + 2) % STAGES, i + 2);
        cp_commit();

        const uint32_t abase = smem0 + (uint32_t)st * STAGE_BYTES;
        const uint32_t bbase = abase + 16384u;

#pragma unroll
        for (int ks = 0; ks < 4; ks++) {
            uint32_t af[4][4];
#pragma unroll
            for (int mt = 0; mt < 4; mt++) {
                int r  = wm + mt * 16 + (lane & 7) + ((lane >> 3) & 1) * 8;
                int kc = ks * 2 + (lane >> 4);
                uint32_t addr = abase + (uint32_t)(r * 128 + ((kc ^ (r & 7)) << 4));
                ldsm_x4(af[mt][0], af[mt][1], af[mt][2], af[mt][3], addr);
            }
            uint32_t bf[4][2];
#pragma unroll
            for (int jp = 0; jp < 2; jp++) {
                int r  = wn + (jp * 2 + (lane >> 4)) * 8 + (lane & 7);
                int kc = ks * 2 + ((lane >> 3) & 1);
                uint32_t addr = bbase + (uint32_t)(r * 128 + ((kc ^ (r & 7)) << 4));
                ldsm_x4(bf[jp * 2][0], bf[jp * 2][1],
                        bf[jp * 2 + 1][0], bf[jp * 2 + 1][1], addr);
            }
#pragma unroll
            for (int mt = 0; mt < 4; mt++)
#pragma unroll
                for (int nt = 0; nt < 4; nt++)
                    mma_tf32(acc[mt][nt], af[mt], bf[nt]);
        }
        __syncthreads();
    }

    // epilogue: c0:(r, c), c1:(r, c+1), c2:(r+8, c), c3:(r+8, c+1)
#pragma unroll
    for (int mt = 0; mt < 4; mt++) {
        int row0 = m0 + wm + mt * 16 + (lane >> 2);
#pragma unroll
        for (int nt = 0; nt < 4; nt++) {
            int col = n0 + wn + nt * 8 + 2 * (lane & 3);
            float v0 = acc[mt][nt][0] * alpha;
            float v1 = acc[mt][nt][1] * alpha;
            float v2 = acc[mt][nt][2] * alpha;
            float v3 = acc[mt][nt][3] * alpha;
            if (roundOut) {
                v0 = tf32r(v0); v1 = tf32r(v1); v2 = tf32r(v2); v3 = tf32r(v3);
            }
            if (row0 < Mvalid)
                *reinterpret_cast<float2*>(C + (size_t)row0 * ldc + col) =
                    make_float2(v0, v1);
            if (row0 + 8 < Mvalid)
                *reinterpret_cast<float2*>(C + (size_t)(row0 + 8) * ldc + col) =
                    make_float2(v2, v3);
        }
    }
}

// ---------------------------------------------------------------------------
// Tiled transpose + tf32 round: out[C,R] = tf32(in[R,C]^T), batched over z
// ---------------------------------------------------------------------------
__global__ void transpose_k(const float* __restrict__ in, float* __restrict__ out,
                            int R, int C, long long sIn, long long sOut)
{
    __shared__ float t[32][33];
    in  += (size_t)blockIdx.z * sIn;
    out += (size_t)blockIdx.z * sOut;
    int c0 = blockIdx.x * 32, r0 = blockIdx.y * 32;
#pragma unroll
    for (int dy = threadIdx.y; dy < 32; dy += 8)
        t[dy][threadIdx.x] = in[(size_t)(r0 + dy) * C + c0 + threadIdx.x];
    __syncthreads();
#pragma unroll
    for (int dy = threadIdx.y; dy < 32; dy += 8)
        out[(size_t)(c0 + dy) * R + r0 + threadIdx.x] = tf32r(t[threadIdx.x][dy]);
}

// ---------------------------------------------------------------------------
// tf32 round-copy (float4)
// ---------------------------------------------------------------------------
__global__ void copy_round(const float* __restrict__ in, float* __restrict__ out,
                           size_t n4)
{
    size_t i = (size_t)blockIdx.x * blockDim.x + threadIdx.x;
    if (i >= n4) return;
    float4 v = reinterpret_cast<const float4*>(in)[i];
    v.x = tf32r(v.x); v.y = tf32r(v.y); v.z = tf32r(v.z); v.w = tf32r(v.w);
    reinterpret_cast<float4*>(out)[i] = v;
}

// ---------------------------------------------------------------------------
// Gather combined QKV [rows,6144] -> padded [B,H,LP,DH] Q,K,V with RoPE,
// outputs tf32-rounded
// ---------------------------------------------------------------------------
__global__ void assemble_rope(const float* __restrict__ QKVv,
                              const float* __restrict__ QKVe,
                              const int* __restrict__ pos_ids,
                              float* __restrict__ Q, float* __restrict__ K,
                              float* __restrict__ V)
{
    int idx = blockIdx.x * blockDim.x + threadIdx.x;
    const int TOTAL = B_ * H_ * LT * (DH_ / 2);
    if (idx >= TOTAL) return;

    int i = idx & 127;
    int t = idx >> 7;
    int l = t % LT;  t /= LT;
    int h = t % H_;
    int b = t / H_;

    int pos = pos_ids[b * LT + l];
    const float LN_BASE_OVER_128 = 9.210340371976184f / 128.0f;
    float ang = (float)pos * expf(-LN_BASE_OVER_128 * (float)i);
    float cs = cosf(ang), sn = sinf(ang);

    const float* srow;
    if (l < LV) srow = QKVv + (size_t)(b * LV + l) * 6144;
    else        srow = QKVe + (size_t)(b * LE + (l - LV)) * 6144;
    size_t so = (size_t)h * DH_ + i;

    size_t dst = (((size_t)(b * H_ + h) * LP) + l) * DH_ + i;

    float q1 = srow[so],        q2 = srow[so + 128];
    float k1 = srow[so + 2048], k2 = srow[so + 2048 + 128];
    float v1 = srow[so + 4096], v2 = srow[so + 4096 + 128];
    Q[dst]       = tf32r(q1 * cs - q2 * sn);
    Q[dst + 128] = tf32r(q2 * cs + q1 * sn);
    K[dst]       = tf32r(k1 * cs - k2 * sn);
    K[dst + 128] = tf32r(k2 * cs + k1 * sn);
    V[dst]       = tf32r(v1);
    V[dst + 128] = tf32r(v2);
}

// ---------------------------------------------------------------------------
// Row softmax over first LT cols (stride LP) + mask; probs rounded to tf32
// ---------------------------------------------------------------------------
__global__ void softmax_rows(float* __restrict__ S, const float* __restrict__ mask)
{
    int row = blockIdx.x;
    int z = row / LT, q = row - z * LT;
    int b = z / H_;
    const float* mrow = mask + ((size_t)b * LT + q) * LT;
    float* srow = S + ((size_t)z * LP + q) * LP;

    __shared__ float red[256];
    int tid = threadIdx.x;

    float m = -1e30f;
    for (int k = tid; k < LT; k += 256) {
        float v = srow[k] + mrow[k];
        srow[k] = v;
        m = fmaxf(m, v);
    }
    red[tid] = m; __syncthreads();
    for (int s = 128; s > 0; s >>= 1) {
        if (tid < s) red[tid] = fmaxf(red[tid], red[tid + s]);
        __syncthreads();
    }
    m = red[0]; __syncthreads();

    float sum = 0.0f;
    for (int k = tid; k < LT; k += 256) {
        float e = __expf(srow[k] - m);
        srow[k] = e;
        sum += e;
    }
    red[tid] = sum; __syncthreads();
    for (int s = 128; s > 0; s >>= 1) {
        if (tid < s) red[tid] += red[tid + s];
        __syncthreads();
    }
    float inv = 1.0f / red[0];
    for (int k = tid; k < LT; k += 256) srow[k] = tf32r(srow[k] * inv);
}

// ---------------------------------------------------------------------------
// Host side
// ---------------------------------------------------------------------------
extern "C" void kernel_launch(void* const* d_in, const int* in_sizes, int n_in,
                              void* d_out, int out_size)
{
    const float* vlm_hidden = (const float*)d_in[0];
    const float* exp_hidden = (const float*)d_in[1];
    const float* attn_mask  = (const float*)d_in[2];
    const int*   pos_ids    = (const int*)  d_in[3];
    const float* wq_v = (const float*)d_in[4];
    const float* wk_v = (const float*)d_in[5];
    const float* wv_v = (const float*)d_in[6];
    const float* wo_v = (const float*)d_in[7];
    const float* wq_e = (const float*)d_in[8];
    const float* wk_e = (const float*)d_in[9];
    const float* wv_e = (const float*)d_in[10];
    const float* wo_e = (const float*)d_in[11];
    float* out = (float*)d_out;

    float* sc = nullptr;
    cudaGetSymbolAddress((void**)&sc, g_scratch);

    float* QKVv = sc + OFF_QKVV;
    float* QKVe = sc + OFF_QKVE;
    float* Q    = sc + OFF_Q;
    float* K    = sc + OFF_K;
    float* V    = sc + OFF_V;
    float* Vt   = sc + OFF_VT;
    float* S    = sc + OFF_S;
    float* AO   = sc + OFF_AO;
    float* WTv  = sc + OFF_WTV;
    float* WTe  = sc + OFF_WTE;
    float* WOv  = sc + OFF_WOV;
    float* WOe  = sc + OFF_WOE;
    float* HIDv = sc + OFF_HIDV;
    float* HIDe = sc + OFF_HIDE;

    cudaFuncSetAttribute((const void*)gemm_mma,
                         cudaFuncAttributeMaxDynamicSharedMemorySize, GEMM_SMEM);

    dim3 tb(32, 8);
    // ---- weight transposes (+tf32 round): W[K,N] -> WT[N,K] ----
    transpose_k<<<dim3(HD/32, DV/32, 1), tb>>>(wq_v, WTv,                   DV, HD, 0, 0);
    transpose_k<<<dim3(HD/32, DV/32, 1), tb>>>(wk_v, WTv + (size_t)2048*DV, DV, HD, 0, 0);
    transpose_k<<<dim3(HD/32, DV/32, 1), tb>>>(wv_v, WTv + (size_t)4096*DV, DV, HD, 0, 0);
    transpose_k<<<dim3(HD/32, DE/32, 1), tb>>>(wq_e, WTe,                   DE, HD, 0, 0);
    transpose_k<<<dim3(HD/32, DE/32, 1), tb>>>(wk_e, WTe + (size_t)2048*DE, DE, HD, 0, 0);
    transpose_k<<<dim3(HD/32, DE/32, 1), tb>>>(wv_e, WTe + (size_t)4096*DE, DE, HD, 0, 0);
    transpose_k<<<dim3(DV/32, HD/32, 1), tb>>>(wo_v, WOv, HD, DV, 0, 0);
    transpose_k<<<dim3(DE/32, HD/32, 1), tb>>>(wo_e, WOe, HD, DE, 0, 0);

    // ---- hidden state round-copies ----
    copy_round<<<(unsigned)((SZ_HIDV/4 + 255)/256), 256>>>(vlm_hidden, HIDv, SZ_HIDV/4);
    copy_round<<<(unsigned)((SZ_HIDE/4 + 255)/256), 256>>>(exp_hidden, HIDe, SZ_HIDE/4);

    // ---- QKV projections (combined N=6144) ----
    gemm_mma<<<dim3(48, 24, 1), 256, GEMM_SMEM>>>(
        HIDv, WTv, QKVv, DV, DV, DV, 6144,
        0,0, 0,0, 0,0, 1, 1.0f, B_*LV, 0);
    gemm_mma<<<dim3(48, 2, 1), 256, GEMM_SMEM>>>(
        HIDe, WTe, QKVe, DE, DE, DE, 6144,
        0,0, 0,0, 0,0, 1, 1.0f, B_*LE, 0);

    // ---- gather + RoPE into padded [B,H,LP,DH] (tf32-rounded) ----
    {
        int total = B_ * H_ * LT * (DH_ / 2);
        assemble_rope<<<(total + 255) / 256, 256>>>(QKVv, QKVe, pos_ids, Q, K, V);
    }

    // ---- V -> Vt per head ([LP,DH] -> [DH,LP]) ----
    transpose_k<<<dim3(DH_/32, LP/32, B_*H_), tb>>>(
        V, Vt, LP, DH_, (long long)LP*DH_, (long long)DH_*LP);

    // ---- scores = SCALE * Q @ K^T ----
    gemm_mma<<<dim3(LP/128, LP/128, B_*H_), 256, GEMM_SMEM>>>(
        Q, K, S, DH_, DH_, DH_, LP,
        0, (long long)LP*DH_, 0, (long long)LP*DH_, 0, (long long)LP*LP,
        B_*H_, SCALE_, LP, 0);

    // ---- softmax (+mask), probs tf32-rounded ----
    softmax_rows<<<B_ * H_ * LT, 256>>>(S, attn_mask);

    // ---- AO = P @ V (B operand Vt[N=dh,K=l]) -> [B,LP,HD], tf32-rounded ----
    gemm_mma<<<dim3(DH_/128, LP/128, B_*H_), 256, GEMM_SMEM>>>(
        S, Vt, AO, LP, LP, LP, HD,
        (long long)H_*LP*LP, (long long)LP*LP,
        (long long)H_*DH_*LP, (long long)DH_*LP,
        (long long)LP*HD, (long long)DH_,
        H_, 1.0f, LP, 1);

    // ---- output projections ----
    gemm_mma<<<dim3(DV/128, LV/128, B_), 256, GEMM_SMEM>>>(
        AO, WOv, out, HD, HD, HD, DV,
        (long long)LP*HD, 0, 0, 0, (long long)LV*DV, 0,
        1, 1.0f, 1 << 30, 0);
    {
        float* out_e = out + (size_t)B_*LV*DV;
        gemm_mma<<<dim3(DE/128, 1, B_), 256, GEMM_SMEM>>>(
            AO + (size_t)LV*HD, WOe, out_e, HD, HD, HD, DE,
            (long long)LP*HD, 0, 0, 0, (long long)LE*DE, 0,
            1, 1.0f, LE, 0);
    }
}

// round 6
// speedup vs baseline: 4.2282x; 1.5808x over previous
#include <cuda_runtime.h>
#include <cuda_fp16.h>
#include <math.h>
#include <cstdint>

// ---------------------------------------------------------------------------
// Problem constants
// ---------------------------------------------------------------------------
static constexpr int B_    = 4;
static constexpr int LV    = 768;
static constexpr int LE    = 64;
static constexpr int LT    = 832;
static constexpr int LP    = 896;    // padded to multiple of 128
static constexpr int DV    = 2048;
static constexpr int DE    = 1024;
static constexpr int H_    = 8;
static constexpr int DH_   = 256;
static constexpr int HD    = 2048;
static constexpr float SCALE_ = 0.0625f;

// ---------------------------------------------------------------------------
// Scratch: single zero-initialized byte array. Pad rows never written stay 0.
// All offsets are multiples of 256 bytes.
// ---------------------------------------------------------------------------
static constexpr size_t BOFF_QKVV = 0;                                   // f32 [B*LV, 6144]
static constexpr size_t BSZ_QKVV  = (size_t)4*B_*LV*6144;
static constexpr size_t BOFF_QKVE = BOFF_QKVV + BSZ_QKVV;                // f32 [B*LE, 6144]
static constexpr size_t BSZ_QKVE  = (size_t)4*B_*LE*6144;
static constexpr size_t BOFF_HIDV = BOFF_QKVE + BSZ_QKVE;                // h [B*LV, DV]
static constexpr size_t BSZ_HIDV  = (size_t)2*B_*LV*DV;
static constexpr size_t BOFF_HIDE = BOFF_HIDV + BSZ_HIDV;                // h [B*LE, DE]
static constexpr size_t BSZ_HIDE  = (size_t)2*B_*LE*DE;
static constexpr size_t BOFF_WTV  = BOFF_HIDE + BSZ_HIDE;                // h [6144, DV]
static constexpr size_t BSZ_WTV   = (size_t)2*6144*DV;
static constexpr size_t BOFF_WTE  = BOFF_WTV + BSZ_WTV;                  // h [6144, DE]
static constexpr size_t BSZ_WTE   = (size_t)2*6144*DE;
static constexpr size_t BOFF_WOV  = BOFF_WTE + BSZ_WTE;                  // h [DV, HD]
static constexpr size_t BSZ_WOV   = (size_t)2*DV*HD;
static constexpr size_t BOFF_WOE  = BOFF_WOV + BSZ_WOV;                  // h [DE, HD]
static constexpr size_t BSZ_WOE   = (size_t)2*DE*HD;
static constexpr size_t BOFF_Q    = BOFF_WOE + BSZ_WOE;                  // h [B,H,LP,DH]
static constexpr size_t BSZ_QP    = (size_t)2*B_*H_*LP*DH_;
static constexpr size_t BOFF_K    = BOFF_Q + BSZ_QP;
static constexpr size_t BOFF_V    = BOFF_K + BSZ_QP;
static constexpr size_t BOFF_VT   = BOFF_V + BSZ_QP;                     // h [B,H,DH,LP]
static constexpr size_t BOFF_S    = BOFF_VT + BSZ_QP;                    // f32 [B,H,LP,LP]
static constexpr size_t BSZ_S     = (size_t)4*B_*H_*LP*LP;
static constexpr size_t BOFF_P    = BOFF_S + BSZ_S;                      // h [B,H,LP,LP]
static constexpr size_t BSZ_P     = (size_t)2*B_*H_*LP*LP;
static constexpr size_t BOFF_AO   = BOFF_P + BSZ_P;                      // h [B,LP,HD]
static constexpr size_t BSZ_AO    = (size_t)2*B_*LP*HD;
static constexpr size_t SCRATCH_BYTES = BOFF_AO + BSZ_AO;

__device__ __align__(256) unsigned char g_scratch[SCRATCH_BYTES];

// ---------------------------------------------------------------------------
// Helpers
// ---------------------------------------------------------------------------
__device__ __forceinline__ uint32_t smem_u32_of(const void* p) {
    uint32_t a;
    asm("{ .reg .u64 t; cvta.to.shared.u64 t, %1; cvt.u32.u64 %0, t; }"
        : "=r"(a) : "l"(p));
    return a;
}
__device__ __forceinline__ void cp_async16(uint32_t saddr, const void* gsrc) {
    asm volatile("cp.async.cg.shared.global [%0], [%1], 16;\n"
                 :: "r"(saddr), "l"(gsrc));
}
__device__ __forceinline__ void cp_commit() {
    asm volatile("cp.async.commit_group;\n");
}
template<int N>
__device__ __forceinline__ void cp_wait() {
    asm volatile("cp.async.wait_group %0;\n" :: "n"(N));
}
__device__ __forceinline__ void ldsm_x4(uint32_t& r0, uint32_t& r1,
                                        uint32_t& r2, uint32_t& r3,
                                        uint32_t addr) {
    asm volatile("ldmatrix.sync.aligned.m8n8.x4.shared.b16 {%0,%1,%2,%3}, [%4];\n"
                 : "=r"(r0), "=r"(r1), "=r"(r2), "=r"(r3) : "r"(addr));
}
__device__ __forceinline__ void mma_f16(float* c, const uint32_t* a,
                                        const uint32_t* b) {
    asm volatile(
        "mma.sync.aligned.m16n8k16.row.col.f32.f16.f16.f32 "
        "{%0,%1,%2,%3}, {%4,%5,%6,%7}, {%8,%9}, {%0,%1,%2,%3};\n"
        : "+f"(c[0]), "+f"(c[1]), "+f"(c[2]), "+f"(c[3])
        : "r"(a[0]), "r"(a[1]), "r"(a[2]), "r"(a[3]), "r"(b[0]), "r"(b[1]));
}
__device__ __forceinline__ uint32_t pack_h2(float a, float b) {
    __half2 h = __floats2half2_rn(a, b);
    uint32_t u;
    memcpy(&u, &h, 4);
    return u;
}

// ---------------------------------------------------------------------------
// fp16 mma.sync GEMM: D[m,n] = alpha * sum_k A[m,k]*B[n,k]  (fp32 accumulate)
// Tile 128x128, BK=64, 3-stage cp.async, 256 threads (8 warps, 64x32 each).
// A,B are __half K-major row-major. N%128==0, K%64==0.
// A-row loads clamped at Mload; C stores guarded by Mstore.
// outHalf selects fp16 vs fp32 C.
// Batched via blockIdx.z: (bb,hh) = (z/Hdiv, z%Hdiv).
// ---------------------------------------------------------------------------
static constexpr int STAGES = 3;
static constexpr int STAGE_BYTES = 2 * 128 * 64 * 2;       // 32 KB (A 16K + B 16K)
static constexpr int GEMM_SMEM = STAGES * STAGE_BYTES + 256;

__global__ __launch_bounds__(256, 2)
void gemm_h(const __half* __restrict__ A, const __half* __restrict__ B,
            void* __restrict__ Cv,
            int Kdim, int lda, int ldb, int ldc,
            long long sAb, long long sAh,
            long long sBb, long long sBh,
            long long sCb, long long sCh,
            int Hdiv, float alpha, int Mload, int Mstore, int outHalf)
{
    long long coff;
    {
        int z  = blockIdx.z;
        int bb = z / Hdiv;
        int hh = z - bb * Hdiv;
        A += bb * sAb + hh * sAh;
        B += bb * sBb + hh * sBh;
        coff = bb * sCb + hh * sCh;
    }
    const int m0  = blockIdx.y * 128;
    const int n0  = blockIdx.x * 128;
    const int tid = threadIdx.x;
    const int wid = tid >> 5;
    const int lane = tid & 31;
    const int wm = (wid >> 2) * 64;      // 2 warp rows
    const int wn = (wid & 3) * 32;       // 4 warp cols

    extern __shared__ float dsm[];
    const uint32_t smem0 = (smem_u32_of(dsm) + 127u) & ~127u;

    // stage: A tile 128x64 h (16KB) then B tile 128x64 h (16KB); rows = 128B
    auto load_stage = [&](int st, int kt) {
        const int k0 = kt * 64;
        const uint32_t sbase = smem0 + (uint32_t)st * STAGE_BYTES;
#pragma unroll
        for (int t = 0; t < 8; t++) {
            int idx = tid + t * 256;           // 0..2047
            int isB = idx >> 10;
            int u   = idx & 1023;
            int r   = u >> 3;                  // row 0..127
            int c   = u & 7;                   // 16B chunk (8 halves)
            uint32_t dst = sbase + (uint32_t)isB * 16384u
                         + (uint32_t)(r * 128 + ((c ^ (r & 7)) << 4));
            const __half* src;
            if (isB) {
                src = B + (size_t)(n0 + r) * ldb + k0 + c * 8;
            } else {
                int rr = (m0 + r < Mload) ? r : 0;
                src = A + (size_t)(m0 + rr) * lda + k0 + c * 8;
            }
            cp_async16(dst, src);
        }
    };

    float acc[4][4][4];
#pragma unroll
    for (int i = 0; i < 4; i++)
#pragma unroll
        for (int j = 0; j < 4; j++)
#pragma unroll
            for (int t = 0; t < 4; t++) acc[i][j][t] = 0.0f;

    const int nk = Kdim / 64;
    load_stage(0, 0); cp_commit();
    load_stage(1, 1); cp_commit();

    for (int i = 0; i < nk; i++) {
        const int st = i % STAGES;
        cp_wait<1>();
        __syncthreads();
        if (i + 2 < nk) load_stage((i + 2) % STAGES, i + 2);
        cp_commit();

        const uint32_t abase = smem0 + (uint32_t)st * STAGE_BYTES;
        const uint32_t bbase = abase + 16384u;

#pragma unroll
        for (int ks = 0; ks < 4; ks++) {       // k16 steps within BK=64
            uint32_t af[4][4];
#pragma unroll
            for (int mt = 0; mt < 4; mt++) {
                int r = wm + mt * 16 + (lane & 7) + ((lane >> 3) & 1) * 8;
                int c = ks * 2 + (lane >> 4);
                uint32_t addr = abase + (uint32_t)(r * 128 + ((c ^ (r & 7)) << 4));
                ldsm_x4(af[mt][0], af[mt][1], af[mt][2], af[mt][3], addr);
            }
            uint32_t bf[4][2];
#pragma unroll
            for (int jp = 0; jp < 2; jp++) {
                int n = wn + jp * 16 + (lane & 7) + ((lane >> 4) & 1) * 8;
                int c = ks * 2 + ((lane >> 3) & 1);
                uint32_t addr = bbase + (uint32_t)(n * 128 + ((c ^ (n & 7)) << 4));
                ldsm_x4(bf[jp * 2][0], bf[jp * 2][1],
                        bf[jp * 2 + 1][0], bf[jp * 2 + 1][1], addr);
            }
#pragma unroll
            for (int mt = 0; mt < 4; mt++)
#pragma unroll
                for (int nt = 0; nt < 4; nt++)
                    mma_f16(acc[mt][nt], af[mt], bf[nt]);
        }
        __syncthreads();
    }

    // epilogue: c0:(r,c) c1:(r,c+1) c2:(r+8,c) c3:(r+8,c+1)
#pragma unroll
    for (int mt = 0; mt < 4; mt++) {
        int row0 = m0 + wm + mt * 16 + (lane >> 2);
#pragma unroll
        for (int nt = 0; nt < 4; nt++) {
            int col = n0 + wn + nt * 8 + 2 * (lane & 3);
            float v0 = acc[mt][nt][0] * alpha;
            float v1 = acc[mt][nt][1] * alpha;
            float v2 = acc[mt][nt][2] * alpha;
            float v3 = acc[mt][nt][3] * alpha;
            if (outHalf) {
                __half* Ch = reinterpret_cast<__half*>(Cv) + coff;
                if (row0 < Mstore) {
                    uint32_t u = pack_h2(v0, v1);
                    *reinterpret_cast<uint32_t*>(Ch + (size_t)row0 * ldc + col) = u;
                }
                if (row0 + 8 < Mstore) {
                    uint32_t u = pack_h2(v2, v3);
                    *reinterpret_cast<uint32_t*>(Ch + (size_t)(row0 + 8) * ldc + col) = u;
                }
            } else {
                float* Cf = reinterpret_cast<float*>(Cv) + coff;
                if (row0 < Mstore)
                    *reinterpret_cast<float2*>(Cf + (size_t)row0 * ldc + col) =
                        make_float2(v0, v1);
                if (row0 + 8 < Mstore)
                    *reinterpret_cast<float2*>(Cf + (size_t)(row0 + 8) * ldc + col) =
                        make_float2(v2, v3);
            }
        }
    }
}

// ---------------------------------------------------------------------------
// Transpose f32 -> f16: out[C,R] = h(in[R,C]^T)
// ---------------------------------------------------------------------------
__global__ void transpose_f2h(const float* __restrict__ in, __half* __restrict__ out,
                              int R, int C)
{
    __shared__ float t[32][33];
    int c0 = blockIdx.x * 32, r0 = blockIdx.y * 32;
#pragma unroll
    for (int dy = threadIdx.y; dy < 32; dy += 8)
        t[dy][threadIdx.x] = in[(size_t)(r0 + dy) * C + c0 + threadIdx.x];
    __syncthreads();
#pragma unroll
    for (int dy = threadIdx.y; dy < 32; dy += 8)
        out[(size_t)(c0 + dy) * R + r0 + threadIdx.x] =
            __float2half_rn(t[threadIdx.x][dy]);
}

// ---------------------------------------------------------------------------
// Transpose f16 -> f16 (batched over z): out[z][C,R] = in[z][R,C]^T
// ---------------------------------------------------------------------------
__global__ void transpose_h2h(const __half* __restrict__ in, __half* __restrict__ out,
                              int R, int C, long long sIn, long long sOut)
{
    __shared__ __half t[32][34];
    in  += (size_t)blockIdx.z * sIn;
    out += (size_t)blockIdx.z * sOut;
    int c0 = blockIdx.x * 32, r0 = blockIdx.y * 32;
#pragma unroll
    for (int dy = threadIdx.y; dy < 32; dy += 8)
        t[dy][threadIdx.x] = in[(size_t)(r0 + dy) * C + c0 + threadIdx.x];
    __syncthreads();
#pragma unroll
    for (int dy = threadIdx.y; dy < 32; dy += 8)
        out[(size_t)(c0 + dy) * R + r0 + threadIdx.x] = t[threadIdx.x][dy];
}

// ---------------------------------------------------------------------------
// f32 -> f16 copy (8 elements/thread)
// ---------------------------------------------------------------------------
__global__ void copy_f2h(const float* __restrict__ in, __half* __restrict__ out,
                         size_t n8)
{
    size_t i = (size_t)blockIdx.x * blockDim.x + threadIdx.x;
    if (i >= n8) return;
    float4 a = reinterpret_cast<const float4*>(in)[2 * i];
    float4 b = reinterpret_cast<const float4*>(in)[2 * i + 1];
    uint4 packed;
    packed.x = pack_h2(a.x, a.y);
    packed.y = pack_h2(a.z, a.w);
    packed.z = pack_h2(b.x, b.y);
    packed.w = pack_h2(b.z, b.w);
    reinterpret_cast<uint4*>(out)[i] = packed;
}

// ---------------------------------------------------------------------------
// Gather combined QKV [rows,6144] f32 -> padded [B,H,LP,DH] h Q,K,V with RoPE
// ---------------------------------------------------------------------------
__global__ void assemble_rope(const float* __restrict__ QKVv,
                              const float* __restrict__ QKVe,
                              const int* __restrict__ pos_ids,
                              __half* __restrict__ Q, __half* __restrict__ K,
                              __half* __restrict__ V)
{
    int idx = blockIdx.x * blockDim.x + threadIdx.x;
    const int TOTAL = B_ * H_ * LT * (DH_ / 2);
    if (idx >= TOTAL) return;

    int i = idx & 127;
    int t = idx >> 7;
    int l = t % LT;  t /= LT;
    int h = t % H_;
    int b = t / H_;

    int pos = pos_ids[b * LT + l];
    const float LN_BASE_OVER_128 = 9.210340371976184f / 128.0f;
    float ang = (float)pos * expf(-LN_BASE_OVER_128 * (float)i);
    float cs = cosf(ang), sn = sinf(ang);

    const float* srow;
    if (l < LV) srow = QKVv + (size_t)(b * LV + l) * 6144;
    else        srow = QKVe + (size_t)(b * LE + (l - LV)) * 6144;
    size_t so = (size_t)h * DH_ + i;

    size_t dst = (((size_t)(b * H_ + h) * LP) + l) * DH_ + i;

    float q1 = srow[so],        q2 = srow[so + 128];
    float k1 = srow[so + 2048], k2 = srow[so + 2048 + 128];
    float v1 = srow[so + 4096], v2 = srow[so + 4096 + 128];
    Q[dst]       = __float2half_rn(q1 * cs - q2 * sn);
    Q[dst + 128] = __float2half_rn(q2 * cs + q1 * sn);
    K[dst]       = __float2half_rn(k1 * cs - k2 * sn);
    K[dst + 128] = __float2half_rn(k2 * cs + k1 * sn);
    V[dst]       = __float2half_rn(v1);
    V[dst + 128] = __float2half_rn(v2);
}

// ---------------------------------------------------------------------------
// Row softmax: read f32 S (stride LP) + mask, write f16 probs to P (stride LP)
// ---------------------------------------------------------------------------
__global__ void softmax_rows(float* __restrict__ S, const float* __restrict__ mask,
                             __half* __restrict__ P)
{
    int row = blockIdx.x;
    int z = row / LT, q = row - z * LT;
    int b = z / H_;
    const float* mrow = mask + ((size_t)b * LT + q) * LT;
    float* srow = S + ((size_t)z * LP + q) * LP;
    __half* prow = P + ((size_t)z * LP + q) * LP;

    __shared__ float red[256];
    int tid = threadIdx.x;

    float m = -1e30f;
    for (int k = tid; k < LT; k += 256) {
        float v = srow[k] + mrow[k];
        srow[k] = v;
        m = fmaxf(m, v);
    }
    red[tid] = m; __syncthreads();
    for (int s = 128; s > 0; s >>= 1) {
        if (tid < s) red[tid] = fmaxf(red[tid], red[tid + s]);
        __syncthreads();
    }
    m = red[0]; __syncthreads();

    float sum = 0.0f;
    for (int k = tid; k < LT; k += 256) {
        float e = __expf(srow[k] - m);
        srow[k] = e;
        sum += e;
    }
    red[tid] = sum; __syncthreads();
    for (int s = 128; s > 0; s >>= 1) {
        if (tid < s) red[tid] += red[tid + s];
        __syncthreads();
    }
    float inv = 1.0f / red[0];
    for (int k = tid; k < LT; k += 256)
        prow[k] = __float2half_rn(srow[k] * inv);
}

// ---------------------------------------------------------------------------
// Host side
// ---------------------------------------------------------------------------
extern "C" void kernel_launch(void* const* d_in, const int* in_sizes, int n_in,
                              void* d_out, int out_size)
{
    const float* vlm_hidden = (const float*)d_in[0];
    const float* exp_hidden = (const float*)d_in[1];
    const float* attn_mask  = (const float*)d_in[2];
    const int*   pos_ids    = (const int*)  d_in[3];
    const float* wq_v = (const float*)d_in[4];
    const float* wk_v = (const float*)d_in[5];
    const float* wv_v = (const float*)d_in[6];
    const float* wo_v = (const float*)d_in[7];
    const float* wq_e = (const float*)d_in[8];
    const float* wk_e = (const float*)d_in[9];
    const float* wv_e = (const float*)d_in[10];
    const float* wo_e = (const float*)d_in[11];
    float* out = (float*)d_out;

    unsigned char* sc = nullptr;
    cudaGetSymbolAddress((void**)&sc, g_scratch);

    float*  QKVv = (float*) (sc + BOFF_QKVV);
    float*  QKVe = (float*) (sc + BOFF_QKVE);
    __half* HIDv = (__half*)(sc + BOFF_HIDV);
    __half* HIDe = (__half*)(sc + BOFF_HIDE);
    __half* WTv  = (__half*)(sc + BOFF_WTV);
    __half* WTe  = (__half*)(sc + BOFF_WTE);
    __half* WOv  = (__half*)(sc + BOFF_WOV);
    __half* WOe  = (__half*)(sc + BOFF_WOE);
    __half* Q    = (__half*)(sc + BOFF_Q);
    __half* K    = (__half*)(sc + BOFF_K);
    __half* V    = (__half*)(sc + BOFF_V);
    __half* Vt   = (__half*)(sc + BOFF_VT);
    float*  S    = (float*) (sc + BOFF_S);
    __half* P    = (__half*)(sc + BOFF_P);
    __half* AO   = (__half*)(sc + BOFF_AO);

    cudaFuncSetAttribute((const void*)gemm_h,
                         cudaFuncAttributeMaxDynamicSharedMemorySize, GEMM_SMEM);

    dim3 tb(32, 8);
    // ---- weight transposes (f32 -> f16): W[K,N] -> WT[N,K] ----
    transpose_f2h<<<dim3(HD/32, DV/32), tb>>>(wq_v, WTv,                   DV, HD);
    transpose_f2h<<<dim3(HD/32, DV/32), tb>>>(wk_v, WTv + (size_t)2048*DV, DV, HD);
    transpose_f2h<<<dim3(HD/32, DV/32), tb>>>(wv_v, WTv + (size_t)4096*DV, DV, HD);
    transpose_f2h<<<dim3(HD/32, DE/32), tb>>>(wq_e, WTe,                   DE, HD);
    transpose_f2h<<<dim3(HD/32, DE/32), tb>>>(wk_e, WTe + (size_t)2048*DE, DE, HD);
    transpose_f2h<<<dim3(HD/32, DE/32), tb>>>(wv_e, WTe + (size_t)4096*DE, DE, HD);
    transpose_f2h<<<dim3(DV/32, HD/32), tb>>>(wo_v, WOv, HD, DV);
    transpose_f2h<<<dim3(DE/32, HD/32), tb>>>(wo_e, WOe, HD, DE);

    // ---- hidden state f32 -> f16 copies ----
    {
        size_t n8v = (size_t)B_*LV*DV/8, n8e = (size_t)B_*LE*DE/8;
        copy_f2h<<<(unsigned)((n8v + 255)/256), 256>>>(vlm_hidden, HIDv, n8v);
        copy_f2h<<<(unsigned)((n8e + 255)/256), 256>>>(exp_hidden, HIDe, n8e);
    }

    // ---- QKV projections (combined N=6144), fp32 out ----
    gemm_h<<<dim3(48, 24, 1), 256, GEMM_SMEM>>>(
        HIDv, WTv, QKVv, DV, DV, DV, 6144,
        0,0, 0,0, 0,0, 1, 1.0f, B_*LV, B_*LV, 0);
    gemm_h<<<dim3(48, 2, 1), 256, GEMM_SMEM>>>(
        HIDe, WTe, QKVe, DE, DE, DE, 6144,
        0,0, 0,0, 0,0, 1, 1.0f, B_*LE, B_*LE, 0);

    // ---- gather + RoPE -> f16 padded [B,H,LP,DH] ----
    {
        int total = B_ * H_ * LT * (DH_ / 2);
        assemble_rope<<<(total + 255) / 256, 256>>>(QKVv, QKVe, pos_ids, Q, K, V);
    }

    // ---- V -> Vt per head ([LP,DH] -> [DH,LP]) ----
    transpose_h2h<<<dim3(DH_/32, LP/32, B_*H_), tb>>>(
        V, Vt, LP, DH_, (long long)LP*DH_, (long long)DH_*LP);

    // ---- scores = SCALE * Q @ K^T -> f32 S (skip pad-q stores) ----
    gemm_h<<<dim3(LP/128, LP/128, B_*H_), 256, GEMM_SMEM>>>(
        Q, K, S, DH_, DH_, DH_, LP,
        (long long)LP*DH_, 0, (long long)LP*DH_, 0, (long long)LP*LP, 0,
        1, SCALE_, LP, LT, 0);

    // ---- softmax (+mask) -> f16 P ----
    softmax_rows<<<B_ * H_ * LT, 256>>>(S, attn_mask, P);

    // ---- AO = P @ V (B operand Vt[N=dh,K=l]) -> f16 [B,LP,HD] ----
    gemm_h<<<dim3(DH_/128, LP/128, B_*H_), 256, GEMM_SMEM>>>(
        P, Vt, AO, LP, LP, LP, HD,
        (long long)H_*LP*LP, (long long)LP*LP,
        (long long)H_*DH_*LP, (long long)DH_*LP,
        (long long)LP*HD, (long long)DH_,
        H_, 1.0f, LP, LT, 1);

    // ---- output projections -> f32 d_out ----
    gemm_h<<<dim3(DV/128, LV/128, B_), 256, GEMM_SMEM>>>(
        AO, WOv, out, HD, HD, HD, DV,
        (long long)LP*HD, 0, 0, 0, (long long)LV*DV, 0,
        1, 1.0f, LV, LV, 0);
    {
        float* out_e = out + (size_t)B_*LV*DV;
        gemm_h<<<dim3(DE/128, 1, B_), 256, GEMM_SMEM>>>(
            AO + (size_t)LV*HD, WOe, out_e, HD, HD, HD, DE,
            (long long)LP*HD, 0, 0, 0, (long long)LE*DE, 0,
            1, 1.0f, LE, LE, 0);
    }
}

// round 7
// speedup vs baseline: 4.7463x; 1.1225x over previous
#include <cuda_runtime.h>
#include <cuda_fp16.h>
#include <math.h>
#include <cstdint>

// ---------------------------------------------------------------------------
// Problem constants
// ---------------------------------------------------------------------------
static constexpr int B_    = 4;
static constexpr int LV    = 768;
static constexpr int LE    = 64;
static constexpr int LT    = 832;
static constexpr int LP    = 896;    // padded to multiple of 128
static constexpr int DV    = 2048;
static constexpr int DE    = 1024;
static constexpr int H_    = 8;
static constexpr int DH_   = 256;
static constexpr int HD    = 2048;
static constexpr float SCALE_ = 0.0625f;

// ---------------------------------------------------------------------------
// Scratch: single zero-initialized byte array. Pad rows never written stay 0.
// ---------------------------------------------------------------------------
static constexpr size_t BOFF_QKVV = 0;                                   // f32 [B*LV, 6144]
static constexpr size_t BSZ_QKVV  = (size_t)4*B_*LV*6144;
static constexpr size_t BOFF_QKVE = BOFF_QKVV + BSZ_QKVV;                // f32 [B*LE, 6144]
static constexpr size_t BSZ_QKVE  = (size_t)4*B_*LE*6144;
static constexpr size_t BOFF_HIDV = BOFF_QKVE + BSZ_QKVE;                // h [B*LV, DV]
static constexpr size_t BSZ_HIDV  = (size_t)2*B_*LV*DV;
static constexpr size_t BOFF_HIDE = BOFF_HIDV + BSZ_HIDV;                // h [B*LE, DE]
static constexpr size_t BSZ_HIDE  = (size_t)2*B_*LE*DE;
static constexpr size_t BOFF_WTV  = BOFF_HIDE + BSZ_HIDE;                // h [6144, DV]
static constexpr size_t BSZ_WTV   = (size_t)2*6144*DV;
static constexpr size_t BOFF_WTE  = BOFF_WTV + BSZ_WTV;                  // h [6144, DE]
static constexpr size_t BSZ_WTE   = (size_t)2*6144*DE;
static constexpr size_t BOFF_WOV  = BOFF_WTE + BSZ_WTE;                  // h [DV, HD]
static constexpr size_t BSZ_WOV   = (size_t)2*DV*HD;
static constexpr size_t BOFF_WOE  = BOFF_WOV + BSZ_WOV;                  // h [DE, HD]
static constexpr size_t BSZ_WOE   = (size_t)2*DE*HD;
static constexpr size_t BOFF_Q    = BOFF_WOE + BSZ_WOE;                  // h [B,H,LP,DH]
static constexpr size_t BSZ_QP    = (size_t)2*B_*H_*LP*DH_;
static constexpr size_t BOFF_K    = BOFF_Q + BSZ_QP;
static constexpr size_t BOFF_V    = BOFF_K + BSZ_QP;
static constexpr size_t BOFF_VT   = BOFF_V + BSZ_QP;                     // h [B,H,DH,LP]
static constexpr size_t BOFF_S    = BOFF_VT + BSZ_QP;                    // f32 [B,H,LP,LP]
static constexpr size_t BSZ_S     = (size_t)4*B_*H_*LP*LP;
static constexpr size_t BOFF_P    = BOFF_S + BSZ_S;                      // h [B,H,LP,LP]
static constexpr size_t BSZ_P     = (size_t)2*B_*H_*LP*LP;
static constexpr size_t BOFF_AO   = BOFF_P + BSZ_P;                      // h [B,LP,HD]
static constexpr size_t BSZ_AO    = (size_t)2*B_*LP*HD;
static constexpr size_t SCRATCH_BYTES = BOFF_AO + BSZ_AO;

__device__ __align__(256) unsigned char g_scratch[SCRATCH_BYTES];

// ---------------------------------------------------------------------------
// Helpers
// ---------------------------------------------------------------------------
__device__ __forceinline__ uint32_t smem_u32_of(const void* p) {
    uint32_t a;
    asm("{ .reg .u64 t; cvta.to.shared.u64 t, %1; cvt.u32.u64 %0, t; }"
        : "=r"(a) : "l"(p));
    return a;
}
__device__ __forceinline__ void cp_async16(uint32_t saddr, const void* gsrc) {
    asm volatile("cp.async.cg.shared.global [%0], [%1], 16;\n"
                 :: "r"(saddr), "l"(gsrc));
}
__device__ __forceinline__ void cp_commit() {
    asm volatile("cp.async.commit_group;\n");
}
template<int N>
__device__ __forceinline__ void cp_wait() {
    asm volatile("cp.async.wait_group %0;\n" :: "n"(N));
}
__device__ __forceinline__ void ldsm_x4(uint32_t& r0, uint32_t& r1,
                                        uint32_t& r2, uint32_t& r3,
                                        uint32_t addr) {
    asm volatile("ldmatrix.sync.aligned.m8n8.x4.shared.b16 {%0,%1,%2,%3}, [%4];\n"
                 : "=r"(r0), "=r"(r1), "=r"(r2), "=r"(r3) : "r"(addr));
}
__device__ __forceinline__ void mma_f16(float* c, const uint32_t* a,
                                        const uint32_t* b) {
    asm volatile(
        "mma.sync.aligned.m16n8k16.row.col.f32.f16.f16.f32 "
        "{%0,%1,%2,%3}, {%4,%5,%6,%7}, {%8,%9}, {%0,%1,%2,%3};\n"
        : "+f"(c[0]), "+f"(c[1]), "+f"(c[2]), "+f"(c[3])
        : "r"(a[0]), "r"(a[1]), "r"(a[2]), "r"(a[3]), "r"(b[0]), "r"(b[1]));
}
__device__ __forceinline__ uint32_t pack_h2(float a, float b) {
    __half2 h = __floats2half2_rn(a, b);
    uint32_t u;
    memcpy(&u, &h, 4);
    return u;
}

// ---------------------------------------------------------------------------
// fp16 mma.sync GEMM: D[m,n] = alpha * sum_k A[m,k]*B[n,k]  (fp32 accumulate)
// Tile 128x128, BK=64, 3-stage cp.async, 256 threads (8 warps, 64x32 each).
// Single barrier per K-iter: the top __syncthreads (after each warp's own
// cp_wait) orders (a) all warps' MMA on stage i-1 before anyone overwrites it,
// and (b) all warps' cp.async contributions to stage i before any ldsm.
// ---------------------------------------------------------------------------
static constexpr int STAGES = 3;
static constexpr int STAGE_BYTES = 2 * 128 * 64 * 2;       // 32 KB (A 16K + B 16K)
static constexpr int GEMM_SMEM = STAGES * STAGE_BYTES + 256;

__global__ __launch_bounds__(256, 2)
void gemm_h(const __half* __restrict__ A, const __half* __restrict__ B,
            void* __restrict__ Cv,
            int Kdim, int lda, int ldb, int ldc,
            long long sAb, long long sAh,
            long long sBb, long long sBh,
            long long sCb, long long sCh,
            int Hdiv, float alpha, int Mload, int Mstore, int outHalf)
{
    long long coff;
    {
        int z  = blockIdx.z;
        int bb = z / Hdiv;
        int hh = z - bb * Hdiv;
        A += bb * sAb + hh * sAh;
        B += bb * sBb + hh * sBh;
        coff = bb * sCb + hh * sCh;
    }
    const int m0  = blockIdx.y * 128;
    const int n0  = blockIdx.x * 128;
    const int tid = threadIdx.x;
    const int wid = tid >> 5;
    const int lane = tid & 31;
    const int wm = (wid >> 2) * 64;      // 2 warp rows
    const int wn = (wid & 3) * 32;       // 4 warp cols

    extern __shared__ float dsm[];
    const uint32_t smem0 = (smem_u32_of(dsm) + 127u) & ~127u;

    // stage: A tile 128x64 h (16KB) then B tile 128x64 h (16KB); rows = 128B
    auto load_stage = [&](int st, int kt) {
        const int k0 = kt * 64;
        const uint32_t sbase = smem0 + (uint32_t)st * STAGE_BYTES;
#pragma unroll
        for (int t = 0; t < 8; t++) {
            int idx = tid + t * 256;           // 0..2047
            int isB = idx >> 10;
            int u   = idx & 1023;
            int r   = u >> 3;                  // row 0..127
            int c   = u & 7;                   // 16B chunk (8 halves)
            uint32_t dst = sbase + (uint32_t)isB * 16384u
                         + (uint32_t)(r * 128 + ((c ^ (r & 7)) << 4));
            const __half* src;
            if (isB) {
                src = B + (size_t)(n0 + r) * ldb + k0 + c * 8;
            } else {
                int rr = (m0 + r < Mload) ? r : 0;
                src = A + (size_t)(m0 + rr) * lda + k0 + c * 8;
            }
            cp_async16(dst, src);
        }
    };

    float acc[4][4][4];
#pragma unroll
    for (int i = 0; i < 4; i++)
#pragma unroll
        for (int j = 0; j < 4; j++)
#pragma unroll
            for (int t = 0; t < 4; t++) acc[i][j][t] = 0.0f;

    const int nk = Kdim / 64;
    load_stage(0, 0); cp_commit();
    load_stage(1, 1); cp_commit();

    for (int i = 0; i < nk; i++) {
        const int st = i % STAGES;
        cp_wait<1>();
        __syncthreads();
        if (i + 2 < nk) load_stage((i + 2) % STAGES, i + 2);
        cp_commit();

        const uint32_t abase = smem0 + (uint32_t)st * STAGE_BYTES;
        const uint32_t bbase = abase + 16384u;

#pragma unroll
        for (int ks = 0; ks < 4; ks++) {       // k16 steps within BK=64
            uint32_t af[4][4];
#pragma unroll
            for (int mt = 0; mt < 4; mt++) {
                int r = wm + mt * 16 + (lane & 7) + ((lane >> 3) & 1) * 8;
                int c = ks * 2 + (lane >> 4);
                uint32_t addr = abase + (uint32_t)(r * 128 + ((c ^ (r & 7)) << 4));
                ldsm_x4(af[mt][0], af[mt][1], af[mt][2], af[mt][3], addr);
            }
            uint32_t bf[4][2];
#pragma unroll
            for (int jp = 0; jp < 2; jp++) {
                int n = wn + jp * 16 + (lane & 7) + ((lane >> 4) & 1) * 8;
                int c = ks * 2 + ((lane >> 3) & 1);
                uint32_t addr = bbase + (uint32_t)(n * 128 + ((c ^ (n & 7)) << 4));
                ldsm_x4(bf[jp * 2][0], bf[jp * 2][1],
                        bf[jp * 2 + 1][0], bf[jp * 2 + 1][1], addr);
            }
#pragma unroll
            for (int mt = 0; mt < 4; mt++)
#pragma unroll
                for (int nt = 0; nt < 4; nt++)
                    mma_f16(acc[mt][nt], af[mt], bf[nt]);
        }
        // no trailing __syncthreads: next iteration's top barrier suffices
    }

    // epilogue: c0:(r,c) c1:(r,c+1) c2:(r+8,c) c3:(r+8,c+1)
#pragma unroll
    for (int mt = 0; mt < 4; mt++) {
        int row0 = m0 + wm + mt * 16 + (lane >> 2);
#pragma unroll
        for (int nt = 0; nt < 4; nt++) {
            int col = n0 + wn + nt * 8 + 2 * (lane & 3);
            float v0 = acc[mt][nt][0] * alpha;
            float v1 = acc[mt][nt][1] * alpha;
            float v2 = acc[mt][nt][2] * alpha;
            float v3 = acc[mt][nt][3] * alpha;
            if (outHalf) {
                __half* Ch = reinterpret_cast<__half*>(Cv) + coff;
                if (row0 < Mstore) {
                    uint32_t u = pack_h2(v0, v1);
                    *reinterpret_cast<uint32_t*>(Ch + (size_t)row0 * ldc + col) = u;
                }
                if (row0 + 8 < Mstore) {
                    uint32_t u = pack_h2(v2, v3);
                    *reinterpret_cast<uint32_t*>(Ch + (size_t)(row0 + 8) * ldc + col) = u;
                }
            } else {
                float* Cf = reinterpret_cast<float*>(Cv) + coff;
                if (row0 < Mstore)
                    *reinterpret_cast<float2*>(Cf + (size_t)row0 * ldc + col) =
                        make_float2(v0, v1);
                if (row0 + 8 < Mstore)
                    *reinterpret_cast<float2*>(Cf + (size_t)(row0 + 8) * ldc + col) =
                        make_float2(v2, v3);
            }
        }
    }
}

// ---------------------------------------------------------------------------
// Transpose f32 -> f16: out[C,R] = h(in[R,C]^T)
// ---------------------------------------------------------------------------
__global__ void transpose_f2h(const float* __restrict__ in, __half* __restrict__ out,
                              int R, int C)
{
    __shared__ float t[32][33];
    int c0 = blockIdx.x * 32, r0 = blockIdx.y * 32;
#pragma unroll
    for (int dy = threadIdx.y; dy < 32; dy += 8)
        t[dy][threadIdx.x] = in[(size_t)(r0 + dy) * C + c0 + threadIdx.x];
    __syncthreads();
#pragma unroll
    for (int dy = threadIdx.y; dy < 32; dy += 8)
        out[(size_t)(c0 + dy) * R + r0 + threadIdx.x] =
            __float2half_rn(t[threadIdx.x][dy]);
}

// ---------------------------------------------------------------------------
// Transpose f16 -> f16 (batched over z): out[z][C,R] = in[z][R,C]^T
// ---------------------------------------------------------------------------
__global__ void transpose_h2h(const __half* __restrict__ in, __half* __restrict__ out,
                              int R, int C, long long sIn, long long sOut)
{
    __shared__ __half t[32][34];
    in  += (size_t)blockIdx.z * sIn;
    out += (size_t)blockIdx.z * sOut;
    int c0 = blockIdx.x * 32, r0 = blockIdx.y * 32;
#pragma unroll
    for (int dy = threadIdx.y; dy < 32; dy += 8)
        t[dy][threadIdx.x] = in[(size_t)(r0 + dy) * C + c0 + threadIdx.x];
    __syncthreads();
#pragma unroll
    for (int dy = threadIdx.y; dy < 32; dy += 8)
        out[(size_t)(c0 + dy) * R + r0 + threadIdx.x] = t[threadIdx.x][dy];
}

// ---------------------------------------------------------------------------
// f32 -> f16 copy (8 elements/thread)
// ---------------------------------------------------------------------------
__global__ void copy_f2h(const float* __restrict__ in, __half* __restrict__ out,
                         size_t n8)
{
    size_t i = (size_t)blockIdx.x * blockDim.x + threadIdx.x;
    if (i >= n8) return;
    float4 a = reinterpret_cast<const float4*>(in)[2 * i];
    float4 b = reinterpret_cast<const float4*>(in)[2 * i + 1];
    uint4 packed;
    packed.x = pack_h2(a.x, a.y);
    packed.y = pack_h2(a.z, a.w);
    packed.z = pack_h2(b.x, b.y);
    packed.w = pack_h2(b.z, b.w);
    reinterpret_cast<uint4*>(out)[i] = packed;
}

// ---------------------------------------------------------------------------
// Gather combined QKV [rows,6144] f32 -> padded [B,H,LP,DH] h Q,K,V with RoPE.
// One thread per (b,h,l, i-pair): i0 = 2*(idx&63); handles dims i0,i0+1 and
// their rotation partners i0+128,i0+129. float2 loads, __half2 stores.
// ---------------------------------------------------------------------------
__global__ void assemble_rope(const float* __restrict__ QKVv,
                              const float* __restrict__ QKVe,
                              const int* __restrict__ pos_ids,
                              __half* __restrict__ Q, __half* __restrict__ K,
                              __half* __restrict__ V)
{
    int idx = blockIdx.x * blockDim.x + threadIdx.x;
    const int TOTAL = B_ * H_ * LT * 64;
    if (idx >= TOTAL) return;

    int i0 = (idx & 63) << 1;
    int t = idx >> 6;
    int l = t % LT;  t /= LT;
    int h = t % H_;
    int b = t / H_;

    float pos = (float)pos_ids[b * LT + l];
    const float LN_BASE_OVER_128 = 9.210340371976184f / 128.0f;
    float cs0, sn0, cs1, sn1;
    __sincosf(pos * __expf(-LN_BASE_OVER_128 * (float)i0), &sn0, &cs0);
    __sincosf(pos * __expf(-LN_BASE_OVER_128 * (float)(i0 + 1)), &sn1, &cs1);

    const float* srow;
    if (l < LV) srow = QKVv + (size_t)(b * LV + l) * 6144;
    else        srow = QKVe + (size_t)(b * LE + (l - LV)) * 6144;
    size_t so = (size_t)h * DH_ + i0;

    float2 qa = *reinterpret_cast<const float2*>(srow + so);
    float2 qb = *reinterpret_cast<const float2*>(srow + so + 128);
    float2 ka = *reinterpret_cast<const float2*>(srow + so + 2048);
    float2 kb = *reinterpret_cast<const float2*>(srow + so + 2048 + 128);
    float2 va = *reinterpret_cast<const float2*>(srow + so + 4096);
    float2 vb = *reinterpret_cast<const float2*>(srow + so + 4096 + 128);

    size_t dst = (((size_t)(b * H_ + h) * LP) + l) * DH_ + i0;

    *reinterpret_cast<uint32_t*>(Q + dst) =
        pack_h2(qa.x * cs0 - qb.x * sn0, qa.y * cs1 - qb.y * sn1);
    *reinterpret_cast<uint32_t*>(Q + dst + 128) =
        pack_h2(qb.x * cs0 + qa.x * sn0, qb.y * cs1 + qa.y * sn1);
    *reinterpret_cast<uint32_t*>(K + dst) =
        pack_h2(ka.x * cs0 - kb.x * sn0, ka.y * cs1 - kb.y * sn1);
    *reinterpret_cast<uint32_t*>(K + dst + 128) =
        pack_h2(kb.x * cs0 + ka.x * sn0, kb.y * cs1 + ka.y * sn1);
    *reinterpret_cast<uint32_t*>(V + dst)       = pack_h2(va.x, va.y);
    *reinterpret_cast<uint32_t*>(V + dst + 128) = pack_h2(vb.x, vb.y);
}

// ---------------------------------------------------------------------------
// Register-resident row softmax: read S once + mask once, write f16 P once.
// One block (256 thr) per real row; each thread holds <=4 elements.
// ---------------------------------------------------------------------------
__global__ __launch_bounds__(256)
void softmax_rows(const float* __restrict__ S, const float* __restrict__ mask,
                  __half* __restrict__ P)
{
    int row = blockIdx.x;
    int z = row / LT, q = row - z * LT;
    int b = z / H_;
    const float* mrow = mask + ((size_t)b * LT + q) * LT;
    const float* srow = S + ((size_t)z * LP + q) * LP;
    __half* prow = P + ((size_t)z * LP + q) * LP;

    const int tid = threadIdx.x;
    const int lane = tid & 31;
    const int warp = tid >> 5;
    __shared__ float red[8];

    float v[4];
    float m = -1e30f;
#pragma unroll
    for (int j = 0; j < 4; j++) {
        int k = tid + j * 256;
        if (k < LT) {
            v[j] = srow[k] + mrow[k];
            m = fmaxf(m, v[j]);
        } else v[j] = -1e30f;
    }
#pragma unroll
    for (int o = 16; o > 0; o >>= 1)
        m = fmaxf(m, __shfl_xor_sync(0xFFFFFFFFu, m, o));
    if (lane == 0) red[warp] = m;
    __syncthreads();
    m = red[lane & 7];
#pragma unroll
    for (int o = 4; o > 0; o >>= 1)
        m = fmaxf(m, __shfl_xor_sync(0xFFFFFFFFu, m, o));
    // all lanes now hold block max (reduction over 8 values broadcast by shfl)

    float sum = 0.0f;
#pragma unroll
    for (int j = 0; j < 4; j++) {
        int k = tid + j * 256;
        if (k < LT) {
            v[j] = __expf(v[j] - m);
            sum += v[j];
        }
    }
#pragma unroll
    for (int o = 16; o > 0; o >>= 1)
        sum += __shfl_xor_sync(0xFFFFFFFFu, sum, o);
    __syncthreads();            // reuse red[] safely
    if (lane == 0) red[warp] = sum;
    __syncthreads();
    sum = red[lane & 7];
#pragma unroll
    for (int o = 4; o > 0; o >>= 1)
        sum += __shfl_xor_sync(0xFFFFFFFFu, sum, o);

    float inv = 1.0f / sum;
#pragma unroll
    for (int j = 0; j < 4; j++) {
        int k = tid + j * 256;
        if (k < LT) prow[k] = __float2half_rn(v[j] * inv);
    }
}

// ---------------------------------------------------------------------------
// Host side
// ---------------------------------------------------------------------------
extern "C" void kernel_launch(void* const* d_in, const int* in_sizes, int n_in,
                              void* d_out, int out_size)
{
    const float* vlm_hidden = (const float*)d_in[0];
    const float* exp_hidden = (const float*)d_in[1];
    const float* attn_mask  = (const float*)d_in[2];
    const int*   pos_ids    = (const int*)  d_in[3];
    const float* wq_v = (const float*)d_in[4];
    const float* wk_v = (const float*)d_in[5];
    const float* wv_v = (const float*)d_in[6];
    const float* wo_v = (const float*)d_in[7];
    const float* wq_e = (const float*)d_in[8];
    const float* wk_e = (const float*)d_in[9];
    const float* wv_e = (const float*)d_in[10];
    const float* wo_e = (const float*)d_in[11];
    float* out = (float*)d_out;

    unsigned char* sc = nullptr;
    cudaGetSymbolAddress((void**)&sc, g_scratch);

    float*  QKVv = (float*) (sc + BOFF_QKVV);
    float*  QKVe = (float*) (sc + BOFF_QKVE);
    __half* HIDv = (__half*)(sc + BOFF_HIDV);
    __half* HIDe = (__half*)(sc + BOFF_HIDE);
    __half* WTv  = (__half*)(sc + BOFF_WTV);
    __half* WTe  = (__half*)(sc + BOFF_WTE);
    __half* WOv  = (__half*)(sc + BOFF_WOV);
    __half* WOe  = (__half*)(sc + BOFF_WOE);
    __half* Q    = (__half*)(sc + BOFF_Q);
    __half* K    = (__half*)(sc + BOFF_K);
    __half* V    = (__half*)(sc + BOFF_V);
    __half* Vt   = (__half*)(sc + BOFF_VT);
    float*  S    = (float*) (sc + BOFF_S);
    __half* P    = (__half*)(sc + BOFF_P);
    __half* AO   = (__half*)(sc + BOFF_AO);

    cudaFuncSetAttribute((const void*)gemm_h,
                         cudaFuncAttributeMaxDynamicSharedMemorySize, GEMM_SMEM);

    dim3 tb(32, 8);
    // ---- weight transposes (f32 -> f16): W[K,N] -> WT[N,K] ----
    transpose_f2h<<<dim3(HD/32, DV/32), tb>>>(wq_v, WTv,                   DV, HD);
    transpose_f2h<<<dim3(HD/32, DV/32), tb>>>(wk_v, WTv + (size_t)2048*DV, DV, HD);
    transpose_f2h<<<dim3(HD/32, DV/32), tb>>>(wv_v, WTv + (size_t)4096*DV, DV, HD);
    transpose_f2h<<<dim3(HD/32, DE/32), tb>>>(wq_e, WTe,                   DE, HD);
    transpose_f2h<<<dim3(HD/32, DE/32), tb>>>(wk_e, WTe + (size_t)2048*DE, DE, HD);
    transpose_f2h<<<dim3(HD/32, DE/32), tb>>>(wv_e, WTe + (size_t)4096*DE, DE, HD);
    transpose_f2h<<<dim3(DV/32, HD/32), tb>>>(wo_v, WOv, HD, DV);
    transpose_f2h<<<dim3(DE/32, HD/32), tb>>>(wo_e, WOe, HD, DE);

    // ---- hidden state f32 -> f16 copies ----
    {
        size_t n8v = (size_t)B_*LV*DV/8, n8e = (size_t)B_*LE*DE/8;
        copy_f2h<<<(unsigned)((n8v + 255)/256), 256>>>(vlm_hidden, HIDv, n8v);
        copy_f2h<<<(unsigned)((n8e + 255)/256), 256>>>(exp_hidden, HIDe, n8e);
    }

    // ---- QKV projections (combined N=6144), fp32 out ----
    gemm_h<<<dim3(48, 24, 1), 256, GEMM_SMEM>>>(
        HIDv, WTv, QKVv, DV, DV, DV, 6144,
        0,0, 0,0, 0,0, 1, 1.0f, B_*LV, B_*LV, 0);
    gemm_h<<<dim3(48, 2, 1), 256, GEMM_SMEM>>>(
        HIDe, WTe, QKVe, DE, DE, DE, 6144,
        0,0, 0,0, 0,0, 1, 1.0f, B_*LE, B_*LE, 0);

    // ---- gather + RoPE -> f16 padded [B,H,LP,DH] ----
    {
        int total = B_ * H_ * LT * 64;
        assemble_rope<<<(total + 255) / 256, 256>>>(QKVv, QKVe, pos_ids, Q, K, V);
    }

    // ---- V -> Vt per head ([LP,DH] -> [DH,LP]) ----
    transpose_h2h<<<dim3(DH_/32, LP/32, B_*H_), tb>>>(
        V, Vt, LP, DH_, (long long)LP*DH_, (long long)DH_*LP);

    // ---- scores = SCALE * Q @ K^T -> f32 S (skip pad-q stores) ----
    gemm_h<<<dim3(LP/128, LP/128, B_*H_), 256, GEMM_SMEM>>>(
        Q, K, S, DH_, DH_, DH_, LP,
        (long long)LP*DH_, 0, (long long)LP*DH_, 0, (long long)LP*LP, 0,
        1, SCALE_, LP, LT, 0);

    // ---- softmax (+mask) -> f16 P (single pass) ----
    softmax_rows<<<B_ * H_ * LT, 256>>>(S, attn_mask, P);

    // ---- AO = P @ V (B operand Vt[N=dh,K=l]), Kdim=LT=832 -> f16 [B,LP,HD] ----
    gemm_h<<<dim3(DH_/128, LP/128, B_*H_), 256, GEMM_SMEM>>>(
        P, Vt, AO, LT, LP, LP, HD,
        (long long)H_*LP*LP, (long long)LP*LP,
        (long long)H_*DH_*LP, (long long)DH_*LP,
        (long long)LP*HD, (long long)DH_,
        H_, 1.0f, LP, LT, 1);

    // ---- output projections -> f32 d_out ----
    gemm_h<<<dim3(DV/128, LV/128, B_), 256, GEMM_SMEM>>>(
        AO, WOv, out, HD, HD, HD, DV,
        (long long)LP*HD, 0, 0, 0, (long long)LV*DV, 0,
        1, 1.0f, LV, LV, 0);
    {
        float* out_e = out + (size_t)B_*LV*DV;
        gemm_h<<<dim3(DE/128, 1, B_), 256, GEMM_SMEM>>>(
            AO + (size_t)LV*HD, WOe, out_e, HD, HD, HD, DE,
            (long long)LP*HD, 0, 0, 0, (long long)LE*DE, 0,
            1, 1.0f, LE, LE, 0);
    }
}

// round 8
// speedup vs baseline: 5.3366x; 1.1244x over previous
#include <cuda_runtime.h>
#include <cuda_fp16.h>
#include <math.h>
#include <cstdint>

// ---------------------------------------------------------------------------
// Problem constants
// ---------------------------------------------------------------------------
static constexpr int B_    = 4;
static constexpr int LV    = 768;
static constexpr int LE    = 64;
static constexpr int LT    = 832;
static constexpr int LP    = 896;    // padded to multiple of 128
static constexpr int DV    = 2048;
static constexpr int DE    = 1024;
static constexpr int H_    = 8;
static constexpr int DH_   = 256;
static constexpr int HD    = 2048;
static constexpr float SCALE_ = 0.0625f;

// ---------------------------------------------------------------------------
// Scratch: single zero-initialized byte array. Pad rows never written stay 0.
// ---------------------------------------------------------------------------
static constexpr size_t BOFF_QKVV = 0;                                   // h [B*LV, 6144]
static constexpr size_t BSZ_QKVV  = (size_t)2*B_*LV*6144;
static constexpr size_t BOFF_QKVE = BOFF_QKVV + BSZ_QKVV;                // h [B*LE, 6144]
static constexpr size_t BSZ_QKVE  = (size_t)2*B_*LE*6144;
static constexpr size_t BOFF_HIDV = BOFF_QKVE + BSZ_QKVE;                // h [B*LV, DV]
static constexpr size_t BSZ_HIDV  = (size_t)2*B_*LV*DV;
static constexpr size_t BOFF_HIDE = BOFF_HIDV + BSZ_HIDV;                // h [B*LE, DE]
static constexpr size_t BSZ_HIDE  = (size_t)2*B_*LE*DE;
static constexpr size_t BOFF_WTV  = BOFF_HIDE + BSZ_HIDE;                // h [6144, DV]
static constexpr size_t BSZ_WTV   = (size_t)2*6144*DV;
static constexpr size_t BOFF_WTE  = BOFF_WTV + BSZ_WTV;                  // h [6144, DE]
static constexpr size_t BSZ_WTE   = (size_t)2*6144*DE;
static constexpr size_t BOFF_WOV  = BOFF_WTE + BSZ_WTE;                  // h [DV, HD]
static constexpr size_t BSZ_WOV   = (size_t)2*DV*HD;
static constexpr size_t BOFF_WOE  = BOFF_WOV + BSZ_WOV;                  // h [DE, HD]
static constexpr size_t BSZ_WOE   = (size_t)2*DE*HD;
static constexpr size_t BOFF_Q    = BOFF_WOE + BSZ_WOE;                  // h [B,H,LP,DH]
static constexpr size_t BSZ_QP    = (size_t)2*B_*H_*LP*DH_;
static constexpr size_t BOFF_K    = BOFF_Q + BSZ_QP;
static constexpr size_t BOFF_V    = BOFF_K + BSZ_QP;
static constexpr size_t BOFF_VT   = BOFF_V + BSZ_QP;                     // h [B,H,DH,LP]
static constexpr size_t BOFF_S    = BOFF_VT + BSZ_QP;                    // f32 [B,H,LP,LP]
static constexpr size_t BSZ_S     = (size_t)4*B_*H_*LP*LP;
static constexpr size_t BOFF_P    = BOFF_S + BSZ_S;                      // h [B,H,LP,LP]
static constexpr size_t BSZ_P     = (size_t)2*B_*H_*LP*LP;
static constexpr size_t BOFF_AO   = BOFF_P + BSZ_P;                      // h [B,LP,HD]
static constexpr size_t BSZ_AO    = (size_t)2*B_*LP*HD;
static constexpr size_t SCRATCH_BYTES = BOFF_AO + BSZ_AO;

__device__ __align__(256) unsigned char g_scratch[SCRATCH_BYTES];

// ---------------------------------------------------------------------------
// Helpers
// ---------------------------------------------------------------------------
__device__ __forceinline__ uint32_t smem_u32_of(const void* p) {
    uint32_t a;
    asm("{ .reg .u64 t; cvta.to.shared.u64 t, %1; cvt.u32.u64 %0, t; }"
        : "=r"(a) : "l"(p));
    return a;
}
__device__ __forceinline__ void cp_async16(uint32_t saddr, const void* gsrc) {
    asm volatile("cp.async.cg.shared.global [%0], [%1], 16;\n"
                 :: "r"(saddr), "l"(gsrc));
}
__device__ __forceinline__ void cp_commit() {
    asm volatile("cp.async.commit_group;\n");
}
template<int N>
__device__ __forceinline__ void cp_wait() {
    asm volatile("cp.async.wait_group %0;\n" :: "n"(N));
}
__device__ __forceinline__ void ldsm_x4(uint32_t& r0, uint32_t& r1,
                                        uint32_t& r2, uint32_t& r3,
                                        uint32_t addr) {
    asm volatile("ldmatrix.sync.aligned.m8n8.x4.shared.b16 {%0,%1,%2,%3}, [%4];\n"
                 : "=r"(r0), "=r"(r1), "=r"(r2), "=r"(r3) : "r"(addr));
}
__device__ __forceinline__ void mma_f16(float* c, const uint32_t* a,
                                        const uint32_t* b) {
    asm volatile(
        "mma.sync.aligned.m16n8k16.row.col.f32.f16.f16.f32 "
        "{%0,%1,%2,%3}, {%4,%5,%6,%7}, {%8,%9}, {%0,%1,%2,%3};\n"
        : "+f"(c[0]), "+f"(c[1]), "+f"(c[2]), "+f"(c[3])
        : "r"(a[0]), "r"(a[1]), "r"(a[2]), "r"(a[3]), "r"(b[0]), "r"(b[1]));
}
__device__ __forceinline__ uint32_t pack_h2(float a, float b) {
    __half2 h = __floats2half2_rn(a, b);
    uint32_t u;
    memcpy(&u, &h, 4);
    return u;
}

// ---------------------------------------------------------------------------
// fp16 mma.sync GEMM (as round 7; single barrier per K-iter)
// ---------------------------------------------------------------------------
static constexpr int STAGES = 3;
static constexpr int STAGE_BYTES = 2 * 128 * 64 * 2;       // 32 KB
static constexpr int GEMM_SMEM = STAGES * STAGE_BYTES + 256;

__global__ __launch_bounds__(256, 2)
void gemm_h(const __half* __restrict__ A, const __half* __restrict__ B,
            void* __restrict__ Cv,
            int Kdim, int lda, int ldb, int ldc,
            long long sAb, long long sAh,
            long long sBb, long long sBh,
            long long sCb, long long sCh,
            int Hdiv, float alpha, int Mload, int Mstore, int outHalf)
{
    long long coff;
    {
        int z  = blockIdx.z;
        int bb = z / Hdiv;
        int hh = z - bb * Hdiv;
        A += bb * sAb + hh * sAh;
        B += bb * sBb + hh * sBh;
        coff = bb * sCb + hh * sCh;
    }
    const int m0  = blockIdx.y * 128;
    const int n0  = blockIdx.x * 128;
    const int tid = threadIdx.x;
    const int wid = tid >> 5;
    const int lane = tid & 31;
    const int wm = (wid >> 2) * 64;
    const int wn = (wid & 3) * 32;

    extern __shared__ float dsm[];
    const uint32_t smem0 = (smem_u32_of(dsm) + 127u) & ~127u;

    auto load_stage = [&](int st, int kt) {
        const int k0 = kt * 64;
        const uint32_t sbase = smem0 + (uint32_t)st * STAGE_BYTES;
#pragma unroll
        for (int t = 0; t < 8; t++) {
            int idx = tid + t * 256;
            int isB = idx >> 10;
            int u   = idx & 1023;
            int r   = u >> 3;
            int c   = u & 7;
            uint32_t dst = sbase + (uint32_t)isB * 16384u
                         + (uint32_t)(r * 128 + ((c ^ (r & 7)) << 4));
            const __half* src;
            if (isB) {
                src = B + (size_t)(n0 + r) * ldb + k0 + c * 8;
            } else {
                int rr = (m0 + r < Mload) ? r : 0;
                src = A + (size_t)(m0 + rr) * lda + k0 + c * 8;
            }
            cp_async16(dst, src);
        }
    };

    float acc[4][4][4];
#pragma unroll
    for (int i = 0; i < 4; i++)
#pragma unroll
        for (int j = 0; j < 4; j++)
#pragma unroll
            for (int t = 0; t < 4; t++) acc[i][j][t] = 0.0f;

    const int nk = Kdim / 64;
    load_stage(0, 0); cp_commit();
    load_stage(1, 1); cp_commit();

    for (int i = 0; i < nk; i++) {
        const int st = i % STAGES;
        cp_wait<1>();
        __syncthreads();
        if (i + 2 < nk) load_stage((i + 2) % STAGES, i + 2);
        cp_commit();

        const uint32_t abase = smem0 + (uint32_t)st * STAGE_BYTES;
        const uint32_t bbase = abase + 16384u;

#pragma unroll
        for (int ks = 0; ks < 4; ks++) {
            uint32_t af[4][4];
#pragma unroll
            for (int mt = 0; mt < 4; mt++) {
                int r = wm + mt * 16 + (lane & 7) + ((lane >> 3) & 1) * 8;
                int c = ks * 2 + (lane >> 4);
                uint32_t addr = abase + (uint32_t)(r * 128 + ((c ^ (r & 7)) << 4));
                ldsm_x4(af[mt][0], af[mt][1], af[mt][2], af[mt][3], addr);
            }
            uint32_t bf[4][2];
#pragma unroll
            for (int jp = 0; jp < 2; jp++) {
                int n = wn + jp * 16 + (lane & 7) + ((lane >> 4) & 1) * 8;
                int c = ks * 2 + ((lane >> 3) & 1);
                uint32_t addr = bbase + (uint32_t)(n * 128 + ((c ^ (n & 7)) << 4));
                ldsm_x4(bf[jp * 2][0], bf[jp * 2][1],
                        bf[jp * 2 + 1][0], bf[jp * 2 + 1][1], addr);
            }
#pragma unroll
            for (int mt = 0; mt < 4; mt++)
#pragma unroll
                for (int nt = 0; nt < 4; nt++)
                    mma_f16(acc[mt][nt], af[mt], bf[nt]);
        }
    }

#pragma unroll
    for (int mt = 0; mt < 4; mt++) {
        int row0 = m0 + wm + mt * 16 + (lane >> 2);
#pragma unroll
        for (int nt = 0; nt < 4; nt++) {
            int col = n0 + wn + nt * 8 + 2 * (lane & 3);
            float v0 = acc[mt][nt][0] * alpha;
            float v1 = acc[mt][nt][1] * alpha;
            float v2 = acc[mt][nt][2] * alpha;
            float v3 = acc[mt][nt][3] * alpha;
            if (outHalf) {
                __half* Ch = reinterpret_cast<__half*>(Cv) + coff;
                if (row0 < Mstore)
                    *reinterpret_cast<uint32_t*>(Ch + (size_t)row0 * ldc + col) =
                        pack_h2(v0, v1);
                if (row0 + 8 < Mstore)
                    *reinterpret_cast<uint32_t*>(Ch + (size_t)(row0 + 8) * ldc + col) =
                        pack_h2(v2, v3);
            } else {
                float* Cf = reinterpret_cast<float*>(Cv) + coff;
                if (row0 < Mstore)
                    *reinterpret_cast<float2*>(Cf + (size_t)row0 * ldc + col) =
                        make_float2(v0, v1);
                if (row0 + 8 < Mstore)
                    *reinterpret_cast<float2*>(Cf + (size_t)(row0 + 8) * ldc + col) =
                        make_float2(v2, v3);
            }
        }
    }
}

// ---------------------------------------------------------------------------
// Transpose f32 -> f16: out[C,R] = h(in[R,C]^T)
// ---------------------------------------------------------------------------
__global__ void transpose_f2h(const float* __restrict__ in, __half* __restrict__ out,
                              int R, int C)
{
    __shared__ float t[32][33];
    int c0 = blockIdx.x * 32, r0 = blockIdx.y * 32;
#pragma unroll
    for (int dy = threadIdx.y; dy < 32; dy += 8)
        t[dy][threadIdx.x] = in[(size_t)(r0 + dy) * C + c0 + threadIdx.x];
    __syncthreads();
#pragma unroll
    for (int dy = threadIdx.y; dy < 32; dy += 8)
        out[(size_t)(c0 + dy) * R + r0 + threadIdx.x] =
            __float2half_rn(t[threadIdx.x][dy]);
}

// ---------------------------------------------------------------------------
// Transpose f16 -> f16 (batched over z)
// ---------------------------------------------------------------------------
__global__ void transpose_h2h(const __half* __restrict__ in, __half* __restrict__ out,
                              int R, int C, long long sIn, long long sOut)
{
    __shared__ __half t[32][34];
    in  += (size_t)blockIdx.z * sIn;
    out += (size_t)blockIdx.z * sOut;
    int c0 = blockIdx.x * 32, r0 = blockIdx.y * 32;
#pragma unroll
    for (int dy = threadIdx.y; dy < 32; dy += 8)
        t[dy][threadIdx.x] = in[(size_t)(r0 + dy) * C + c0 + threadIdx.x];
    __syncthreads();
#pragma unroll
    for (int dy = threadIdx.y; dy < 32; dy += 8)
        out[(size_t)(c0 + dy) * R + r0 + threadIdx.x] = t[threadIdx.x][dy];
}

// ---------------------------------------------------------------------------
// f32 -> f16 copy (8 elements/thread)
// ---------------------------------------------------------------------------
__global__ void copy_f2h(const float* __restrict__ in, __half* __restrict__ out,
                         size_t n8)
{
    size_t i = (size_t)blockIdx.x * blockDim.x + threadIdx.x;
    if (i >= n8) return;
    float4 a = reinterpret_cast<const float4*>(in)[2 * i];
    float4 b = reinterpret_cast<const float4*>(in)[2 * i + 1];
    uint4 packed;
    packed.x = pack_h2(a.x, a.y);
    packed.y = pack_h2(a.z, a.w);
    packed.z = pack_h2(b.x, b.y);
    packed.w = pack_h2(b.z, b.w);
    reinterpret_cast<uint4*>(out)[i] = packed;
}

// ---------------------------------------------------------------------------
// Gather combined f16 QKV [rows,6144] -> padded [B,H,LP,DH] h Q,K,V with RoPE
// ---------------------------------------------------------------------------
__global__ void assemble_rope(const __half* __restrict__ QKVv,
                              const __half* __restrict__ QKVe,
                              const int* __restrict__ pos_ids,
                              __half* __restrict__ Q, __half* __restrict__ K,
                              __half* __restrict__ V)
{
    int idx = blockIdx.x * blockDim.x + threadIdx.x;
    const int TOTAL = B_ * H_ * LT * 64;
    if (idx >= TOTAL) return;

    int i0 = (idx & 63) << 1;
    int t = idx >> 6;
    int l = t % LT;  t /= LT;
    int h = t % H_;
    int b = t / H_;

    float pos = (float)pos_ids[b * LT + l];
    const float LN_BASE_OVER_128 = 9.210340371976184f / 128.0f;
    float cs0, sn0, cs1, sn1;
    __sincosf(pos * __expf(-LN_BASE_OVER_128 * (float)i0), &sn0, &cs0);
    __sincosf(pos * __expf(-LN_BASE_OVER_128 * (float)(i0 + 1)), &sn1, &cs1);

    const __half* srow;
    if (l < LV) srow = QKVv + (size_t)(b * LV + l) * 6144;
    else        srow = QKVe + (size_t)(b * LE + (l - LV)) * 6144;
    size_t so = (size_t)h * DH_ + i0;

    float2 qa = __half22float2(*reinterpret_cast<const __half2*>(srow + so));
    float2 qb = __half22float2(*reinterpret_cast<const __half2*>(srow + so + 128));
    float2 ka = __half22float2(*reinterpret_cast<const __half2*>(srow + so + 2048));
    float2 kb = __half22float2(*reinterpret_cast<const __half2*>(srow + so + 2048 + 128));
    uint32_t vpa = *reinterpret_cast<const uint32_t*>(srow + so + 4096);
    uint32_t vpb = *reinterpret_cast<const uint32_t*>(srow + so + 4096 + 128);

    size_t dst = (((size_t)(b * H_ + h) * LP) + l) * DH_ + i0;

    *reinterpret_cast<uint32_t*>(Q + dst) =
        pack_h2(qa.x * cs0 - qb.x * sn0, qa.y * cs1 - qb.y * sn1);
    *reinterpret_cast<uint32_t*>(Q + dst + 128) =
        pack_h2(qb.x * cs0 + qa.x * sn0, qb.y * cs1 + qa.y * sn1);
    *reinterpret_cast<uint32_t*>(K + dst) =
        pack_h2(ka.x * cs0 - kb.x * sn0, ka.y * cs1 - kb.y * sn1);
    *reinterpret_cast<uint32_t*>(K + dst + 128) =
        pack_h2(kb.x * cs0 + ka.x * sn0, kb.y * cs1 + ka.y * sn1);
    *reinterpret_cast<uint32_t*>(V + dst)       = vpa;
    *reinterpret_cast<uint32_t*>(V + dst + 128) = vpb;
}

// ---------------------------------------------------------------------------
// Register-resident row softmax (as round 7)
// ---------------------------------------------------------------------------
__global__ __launch_bounds__(256)
void softmax_rows(const float* __restrict__ S, const float* __restrict__ mask,
                  __half* __restrict__ P)
{
    int row = blockIdx.x;
    int z = row / LT, q = row - z * LT;
    int b = z / H_;
    const float* mrow = mask + ((size_t)b * LT + q) * LT;
    const float* srow = S + ((size_t)z * LP + q) * LP;
    __half* prow = P + ((size_t)z * LP + q) * LP;

    const int tid = threadIdx.x;
    const int lane = tid & 31;
    const int warp = tid >> 5;
    __shared__ float red[8];

    float v[4];
    float m = -1e30f;
#pragma unroll
    for (int j = 0; j < 4; j++) {
        int k = tid + j * 256;
        if (k < LT) {
            v[j] = srow[k] + mrow[k];
            m = fmaxf(m, v[j]);
        } else v[j] = -1e30f;
    }
#pragma unroll
    for (int o = 16; o > 0; o >>= 1)
        m = fmaxf(m, __shfl_xor_sync(0xFFFFFFFFu, m, o));
    if (lane == 0) red[warp] = m;
    __syncthreads();
    m = red[lane & 7];
#pragma unroll
    for (int o = 4; o > 0; o >>= 1)
        m = fmaxf(m, __shfl_xor_sync(0xFFFFFFFFu, m, o));

    float sum = 0.0f;
#pragma unroll
    for (int j = 0; j < 4; j++) {
        int k = tid + j * 256;
        if (k < LT) {
            v[j] = __expf(v[j] - m);
            sum += v[j];
        }
    }
#pragma unroll
    for (int o = 16; o > 0; o >>= 1)
        sum += __shfl_xor_sync(0xFFFFFFFFu, sum, o);
    __syncthreads();
    if (lane == 0) red[warp] = sum;
    __syncthreads();
    sum = red[lane & 7];
#pragma unroll
    for (int o = 4; o > 0; o >>= 1)
        sum += __shfl_xor_sync(0xFFFFFFFFu, sum, o);

    float inv = 1.0f / sum;
#pragma unroll
    for (int j = 0; j < 4; j++) {
        int k = tid + j * 256;
        if (k < LT) prow[k] = __float2half_rn(v[j] * inv);
    }
}

// ---------------------------------------------------------------------------
// Host side — second stream for independent branches (captured via events)
// ---------------------------------------------------------------------------
extern "C" void kernel_launch(void* const* d_in, const int* in_sizes, int n_in,
                              void* d_out, int out_size)
{
    const float* vlm_hidden = (const float*)d_in[0];
    const float* exp_hidden = (const float*)d_in[1];
    const float* attn_mask  = (const float*)d_in[2];
    const int*   pos_ids    = (const int*)  d_in[3];
    const float* wq_v = (const float*)d_in[4];
    const float* wk_v = (const float*)d_in[5];
    const float* wv_v = (const float*)d_in[6];
    const float* wo_v = (const float*)d_in[7];
    const float* wq_e = (const float*)d_in[8];
    const float* wk_e = (const float*)d_in[9];
    const float* wv_e = (const float*)d_in[10];
    const float* wo_e = (const float*)d_in[11];
    float* out = (float*)d_out;

    unsigned char* sc = nullptr;
    cudaGetSymbolAddress((void**)&sc, g_scratch);

    __half* QKVv = (__half*)(sc + BOFF_QKVV);
    __half* QKVe = (__half*)(sc + BOFF_QKVE);
    __half* HIDv = (__half*)(sc + BOFF_HIDV);
    __half* HIDe = (__half*)(sc + BOFF_HIDE);
    __half* WTv  = (__half*)(sc + BOFF_WTV);
    __half* WTe  = (__half*)(sc + BOFF_WTE);
    __half* WOv  = (__half*)(sc + BOFF_WOV);
    __half* WOe  = (__half*)(sc + BOFF_WOE);
    __half* Q    = (__half*)(sc + BOFF_Q);
    __half* K    = (__half*)(sc + BOFF_K);
    __half* V    = (__half*)(sc + BOFF_V);
    __half* Vt   = (__half*)(sc + BOFF_VT);
    float*  S    = (float*) (sc + BOFF_S);
    __half* P    = (__half*)(sc + BOFF_P);
    __half* AO   = (__half*)(sc + BOFF_AO);

    static cudaStream_t s1 = nullptr;
    static cudaEvent_t evFork = nullptr, evJoin1 = nullptr,
                       evFork2 = nullptr, evJoin2 = nullptr;
    if (s1 == nullptr) {
        cudaStreamCreateWithFlags(&s1, cudaStreamNonBlocking);
        cudaEventCreateWithFlags(&evFork,  cudaEventDisableTiming);
        cudaEventCreateWithFlags(&evJoin1, cudaEventDisableTiming);
        cudaEventCreateWithFlags(&evFork2, cudaEventDisableTiming);
        cudaEventCreateWithFlags(&evJoin2, cudaEventDisableTiming);
        cudaFuncSetAttribute((const void*)gemm_h,
                             cudaFuncAttributeMaxDynamicSharedMemorySize, GEMM_SMEM);
    }

    dim3 tb(32, 8);

    // ---- fork: expert/prep branch on s1 ----
    cudaEventRecord(evFork, 0);
    cudaStreamWaitEvent(s1, evFork, 0);

    // s1: expert weight transposes + out-proj weights + expert hidden + exp QKV
    transpose_f2h<<<dim3(HD/32, DE/32), tb, 0, s1>>>(wq_e, WTe,                   DE, HD);
    transpose_f2h<<<dim3(HD/32, DE/32), tb, 0, s1>>>(wk_e, WTe + (size_t)2048*DE, DE, HD);
    transpose_f2h<<<dim3(HD/32, DE/32), tb, 0, s1>>>(wv_e, WTe + (size_t)4096*DE, DE, HD);
    transpose_f2h<<<dim3(DV/32, HD/32), tb, 0, s1>>>(wo_v, WOv, HD, DV);
    transpose_f2h<<<dim3(DE/32, HD/32), tb, 0, s1>>>(wo_e, WOe, HD, DE);
    {
        size_t n8e = (size_t)B_*LE*DE/8;
        copy_f2h<<<(unsigned)((n8e + 255)/256), 256, 0, s1>>>(exp_hidden, HIDe, n8e);
    }
    gemm_h<<<dim3(48, 2, 1), 256, GEMM_SMEM, s1>>>(
        HIDe, WTe, QKVe, DE, DE, DE, 6144,
        0,0, 0,0, 0,0, 1, 1.0f, B_*LE, B_*LE, 1);
    cudaEventRecord(evJoin1, s1);

    // stream0: vlm weight transposes + hidden copy + vlm QKV GEMM
    transpose_f2h<<<dim3(HD/32, DV/32), tb>>>(wq_v, WTv,                   DV, HD);
    transpose_f2h<<<dim3(HD/32, DV/32), tb>>>(wk_v, WTv + (size_t)2048*DV, DV, HD);
    transpose_f2h<<<dim3(HD/32, DV/32), tb>>>(wv_v, WTv + (size_t)4096*DV, DV, HD);
    {
        size_t n8v = (size_t)B_*LV*DV/8;
        copy_f2h<<<(unsigned)((n8v + 255)/256), 256>>>(vlm_hidden, HIDv, n8v);
    }
    gemm_h<<<dim3(48, 24, 1), 256, GEMM_SMEM>>>(
        HIDv, WTv, QKVv, DV, DV, DV, 6144,
        0,0, 0,0, 0,0, 1, 1.0f, B_*LV, B_*LV, 1);

    // join expert branch before rope
    cudaStreamWaitEvent(0, evJoin1, 0);

    // ---- gather + RoPE -> f16 padded [B,H,LP,DH] ----
    {
        int total = B_ * H_ * LT * 64;
        assemble_rope<<<(total + 255) / 256, 256>>>(QKVv, QKVe, pos_ids, Q, K, V);
    }

    // ---- V -> Vt per head ----
    transpose_h2h<<<dim3(DH_/32, LP/32, B_*H_), tb>>>(
        V, Vt, LP, DH_, (long long)LP*DH_, (long long)DH_*LP);

    // ---- scores = SCALE * Q @ K^T -> f32 S ----
    gemm_h<<<dim3(LP/128, LP/128, B_*H_), 256, GEMM_SMEM>>>(
        Q, K, S, DH_, DH_, DH_, LP,
        (long long)LP*DH_, 0, (long long)LP*DH_, 0, (long long)LP*LP, 0,
        1, SCALE_, LP, LT, 0);

    // ---- softmax (+mask) -> f16 P ----
    softmax_rows<<<B_ * H_ * LT, 256>>>(S, attn_mask, P);

    // ---- AO = P @ V, Kdim=LT -> f16 [B,LP,HD] ----
    gemm_h<<<dim3(DH_/128, LP/128, B_*H_), 256, GEMM_SMEM>>>(
        P, Vt, AO, LT, LP, LP, HD,
        (long long)H_*LP*LP, (long long)LP*LP,
        (long long)H_*DH_*LP, (long long)DH_*LP,
        (long long)LP*HD, (long long)DH_,
        H_, 1.0f, LP, LT, 1);

    // ---- fork: expert output projection on s1; vlm on stream0 ----
    cudaEventRecord(evFork2, 0);
    cudaStreamWaitEvent(s1, evFork2, 0);
    {
        float* out_e = out + (size_t)B_*LV*DV;
        gemm_h<<<dim3(DE/128, 1, B_), 256, GEMM_SMEM, s1>>>(
            AO + (size_t)LV*HD, WOe, out_e, HD, HD, HD, DE,
            (long long)LP*HD, 0, 0, 0, (long long)LE*DE, 0,
            1, 1.0f, LE, LE, 0);
    }
    cudaEventRecord(evJoin2, s1);

    gemm_h<<<dim3(DV/128, LV/128, B_), 256, GEMM_SMEM>>>(
        AO, WOv, out, HD, HD, HD, DV,
        (long long)LP*HD, 0, 0, 0, (long long)LV*DV, 0,
        1, 1.0f, LV, LV, 0);

    cudaStreamWaitEvent(0, evJoin2, 0);
}